// round 12
// baseline (speedup 1.0000x reference)
#include <cuda_runtime.h>
#include <cuda_bf16.h>
#include <math.h>
#include <stdint.h>

#define NN 50000
#define EE 800000
#define IN_DIM 128
#define HH 4
#define NEG_SLOPE 0.2f
#define NBLK_SCAN 196
#define MTILE 128
#define NCTA_GEMM 391
#define TS 136
#define TILE_U16 (128 * TS)
#define TILE_B (TILE_U16 * 2)
#define NTHR 512

// ---------------- scratch ----------------
__device__ float g_feat[(size_t)NN * IN_DIM];
__device__ float g_el[NN * HH];
__device__ float g_er[NN * HH];
__device__ int   g_cnt[NN];
__device__ int   g_off[NN];
__device__ int   g_cur[NN];
__device__ int   g_esrc[EE];
__device__ int   g_bsum[256];
__device__ __align__(16) unsigned short g_WfcT[2 * TILE_U16];
__device__ __align__(16) unsigned short g_WpT[2 * TILE_U16];
__device__ __align__(16) unsigned short g_WgT[4 * TILE_U16];

// ---------------- helpers ----------------
__device__ __forceinline__ unsigned short bfb(__nv_bfloat16 v) {
    return *reinterpret_cast<unsigned short*>(&v);
}
__device__ __forceinline__ void split2(float x0, float x1, uint32_t& hi, uint32_t& lo) {
    __nv_bfloat16 h0 = __float2bfloat16(x0), h1 = __float2bfloat16(x1);
    __nv_bfloat16 l0 = __float2bfloat16(x0 - __bfloat162float(h0));
    __nv_bfloat16 l1 = __float2bfloat16(x1 - __bfloat162float(h1));
    hi = (uint32_t)bfb(h0) | ((uint32_t)bfb(h1) << 16);
    lo = (uint32_t)bfb(l0) | ((uint32_t)bfb(l1) << 16);
}
__device__ __forceinline__ float2 recon2(const unsigned short* Hi, const unsigned short* Lo, int idx) {
    __nv_bfloat162 h = *(const __nv_bfloat162*)&Hi[idx];
    __nv_bfloat162 l = *(const __nv_bfloat162*)&Lo[idx];
    float2 hf = __bfloat1622float2(h);
    float2 lf = __bfloat1622float2(l);
    return make_float2(hf.x + lf.x, hf.y + lf.y);
}
__device__ __forceinline__ void hmma(float* c, uint32_t a0, uint32_t a1, uint32_t a2, uint32_t a3,
                                     uint32_t b0, uint32_t b1) {
    asm volatile(
        "mma.sync.aligned.m16n8k16.row.col.f32.bf16.bf16.f32 "
        "{%0,%1,%2,%3}, {%4,%5,%6,%7}, {%8,%9}, {%0,%1,%2,%3};"
        : "+f"(c[0]), "+f"(c[1]), "+f"(c[2]), "+f"(c[3])
        : "r"(a0), "r"(a1), "r"(a2), "r"(a3), "r"(b0), "r"(b1));
}

template <int NT>
__device__ __forceinline__ void gemm_tile(float acc[2][NT][4],
    const uint32_t* Ahi, const uint32_t* Alo,
    const uint32_t* Bhi, const uint32_t* Blo,
    int m0, int n0, int g, int t) {
#pragma unroll
    for (int ks = 0; ks < 8; ks++) {
        int k0 = ks * 16;
        uint32_t ah[2][4], al[2][4];
#pragma unroll
        for (int mt = 0; mt < 2; mt++) {
            int r = m0 + mt * 16 + g;
            int i0 = (r * TS + k0 + 2 * t) >> 1;
            int i1 = ((r + 8) * TS + k0 + 2 * t) >> 1;
            ah[mt][0] = Ahi[i0]; ah[mt][1] = Ahi[i1];
            ah[mt][2] = Ahi[i0 + 4]; ah[mt][3] = Ahi[i1 + 4];
            al[mt][0] = Alo[i0]; al[mt][1] = Alo[i1];
            al[mt][2] = Alo[i0 + 4]; al[mt][3] = Alo[i1 + 4];
        }
#pragma unroll
        for (int nt = 0; nt < NT; nt++) {
            int c = n0 + nt * 8 + g;
            int bi = (c * TS + k0 + 2 * t) >> 1;
            uint32_t bh0 = Bhi[bi], bh1 = Bhi[bi + 4];
            uint32_t bl0 = Blo[bi], bl1 = Blo[bi + 4];
#pragma unroll
            for (int mt = 0; mt < 2; mt++) {
                hmma(acc[mt][nt], ah[mt][0], ah[mt][1], ah[mt][2], ah[mt][3], bh0, bh1);
                hmma(acc[mt][nt], ah[mt][0], ah[mt][1], ah[mt][2], ah[mt][3], bl0, bl1);
                hmma(acc[mt][nt], al[mt][0], al[mt][1], al[mt][2], al[mt][3], bh0, bh1);
            }
        }
    }
}

__device__ __forceinline__ void fill_A(unsigned short* Ahi, unsigned short* Alo,
                                       const float* __restrict__ src, long nodebase,
                                       int tid) {
    int m = tid >> 2, q = tid & 3;
    long node = nodebase + m;
    const float* row = src + node * IN_DIM + q * 32;
    uint32_t* H = (uint32_t*)Ahi;
    uint32_t* L = (uint32_t*)Alo;
#pragma unroll
    for (int k4 = 0; k4 < 32; k4 += 4) {
        float4 v = make_float4(0.f, 0.f, 0.f, 0.f);
        if (node < NN) v = *(const float4*)(row + k4);
        uint32_t h01, l01, h23, l23;
        split2(v.x, v.y, h01, l01);
        split2(v.z, v.w, h23, l23);
        int idx = (m * TS + q * 32 + k4) >> 1;
        H[idx] = h01; H[idx + 1] = h23;
        L[idx] = l01; L[idx + 1] = l23;
    }
}

__device__ __forceinline__ void copy_B(unsigned short* dst, const unsigned short* src, int tid) {
    const uint4* s = (const uint4*)src;
    uint4* d = (uint4*)dst;
#pragma unroll
    for (int i = tid; i < 2 * TILE_B / 16; i += NTHR) d[i] = s[i];
}

// ---------------- small kernels ----------------
__global__ void k_init() {
    int i = blockIdx.x * blockDim.x + threadIdx.x;
    if (i < NN) { g_cnt[i] = 0; g_cur[i] = 0; }
}

__global__ void k_hist(const int* __restrict__ dst) {
    int e = blockIdx.x * blockDim.x + threadIdx.x;
    if (e < EE) atomicAdd(&g_cnt[dst[e]], 1);
}

__global__ void k_prepw_fc(const float* __restrict__ Wfc) {
    int id = blockIdx.x * 256 + threadIdx.x;
    if (id >= 16384) return;
    int n = id >> 7, k = id & 127;
    float w = Wfc[k * 128 + n];
    __nv_bfloat16 hi = __float2bfloat16(w);
    __nv_bfloat16 lo = __float2bfloat16(w - __bfloat162float(hi));
    g_WfcT[n * TS + k] = bfb(hi);
    g_WfcT[TILE_U16 + n * TS + k] = bfb(lo);
}

__global__ void k_prepw_pg(const float* __restrict__ Wp, const float* __restrict__ Wg) {
    int id = blockIdx.x * 256 + threadIdx.x;
    if (id < 16384) {
        int n = id >> 7, k = id & 127;
        float w = Wp[k * 128 + n];
        __nv_bfloat16 hi = __float2bfloat16(w);
        __nv_bfloat16 lo = __float2bfloat16(w - __bfloat162float(hi));
        g_WpT[n * TS + k] = bfb(hi);
        g_WpT[TILE_U16 + n * TS + k] = bfb(lo);
    } else if (id < 49152) {
        int e = id - 16384;
        int n = e & 127, k = e >> 7;
        float w = Wg[k * 128 + n];
        int stage = k >> 7, kk = k & 127;
        __nv_bfloat16 hi = __float2bfloat16(w);
        __nv_bfloat16 lo = __float2bfloat16(w - __bfloat162float(hi));
        g_WgT[stage * 2 * TILE_U16 + n * TS + kk] = bfb(hi);
        g_WgT[stage * 2 * TILE_U16 + TILE_U16 + n * TS + kk] = bfb(lo);
    }
}

// ---------------- feat = h @ W_fc, fused el/er ----------------
__global__ void __launch_bounds__(NTHR, 1) k_feat_tc(const float* __restrict__ h,
                                                     const float* __restrict__ al,
                                                     const float* __restrict__ ar) {
    extern __shared__ __align__(16) unsigned short sm[];
    unsigned short* Ahi = sm;
    unsigned short* Alo = sm + TILE_U16;
    unsigned short* Bt  = sm + 2 * TILE_U16;
    int tid = threadIdx.x, wid = tid >> 5, lane = tid & 31;
    int g = lane >> 2, t = lane & 3;
    long nodebase = (long)blockIdx.x * MTILE;

    fill_A(Ahi, Alo, h, nodebase, tid);
    copy_B(Bt, g_WfcT, tid);
    __syncthreads();

    float acc[2][4][4];
#pragma unroll
    for (int a = 0; a < 2; a++)
#pragma unroll
        for (int b = 0; b < 4; b++)
#pragma unroll
            for (int c = 0; c < 4; c++) acc[a][b][c] = 0.f;

    int m0 = (wid >> 2) * 32, n0 = (wid & 3) * 32;
    gemm_tile<4>(acc, (const uint32_t*)Ahi, (const uint32_t*)Alo,
                 (const uint32_t*)Bt, (const uint32_t*)(Bt + TILE_U16), m0, n0, g, t);

    int head = wid & 3;
    float pl[4] = {0.f, 0.f, 0.f, 0.f};
    float pr[4] = {0.f, 0.f, 0.f, 0.f};
#pragma unroll
    for (int nt = 0; nt < 4; nt++) {
        int col = n0 + nt * 8 + 2 * t;
        float a0 = __ldg(&al[col]), a1 = __ldg(&al[col + 1]);
        float b0 = __ldg(&ar[col]), b1 = __ldg(&ar[col + 1]);
#pragma unroll
        for (int mt = 0; mt < 2; mt++) {
            pl[2 * mt]     += acc[mt][nt][0] * a0 + acc[mt][nt][1] * a1;
            pl[2 * mt + 1] += acc[mt][nt][2] * a0 + acc[mt][nt][3] * a1;
            pr[2 * mt]     += acc[mt][nt][0] * b0 + acc[mt][nt][1] * b1;
            pr[2 * mt + 1] += acc[mt][nt][2] * b0 + acc[mt][nt][3] * b1;
        }
    }
#pragma unroll
    for (int off = 1; off <= 2; off <<= 1) {
#pragma unroll
        for (int i = 0; i < 4; i++) {
            pl[i] += __shfl_xor_sync(0xffffffffu, pl[i], off);
            pr[i] += __shfl_xor_sync(0xffffffffu, pr[i], off);
        }
    }
    if (t == 0) {
#pragma unroll
        for (int mt = 0; mt < 2; mt++) {
            long r0 = nodebase + m0 + mt * 16 + g;
            long r1 = r0 + 8;
            if (r0 < NN) { g_el[r0 * HH + head] = pl[2 * mt];     g_er[r0 * HH + head] = pr[2 * mt]; }
            if (r1 < NN) { g_el[r1 * HH + head] = pl[2 * mt + 1]; g_er[r1 * HH + head] = pr[2 * mt + 1]; }
        }
    }

#pragma unroll
    for (int mt = 0; mt < 2; mt++) {
        long r0 = nodebase + m0 + mt * 16 + g;
        long r1 = r0 + 8;
#pragma unroll
        for (int nt = 0; nt < 4; nt++) {
            int col = n0 + nt * 8 + 2 * t;
            if (r0 < NN) *(float2*)&g_feat[r0 * IN_DIM + col] = make_float2(acc[mt][nt][0], acc[mt][nt][1]);
            if (r1 < NN) *(float2*)&g_feat[r1 * IN_DIM + col] = make_float2(acc[mt][nt][2], acc[mt][nt][3]);
        }
    }
}

// ---------------- scans / scatter ----------------
__global__ void k_scan1() {
    __shared__ int s[256];
    int i = blockIdx.x * 256 + threadIdx.x;
    int v = (i < NN) ? g_cnt[i] : 0;
    s[threadIdx.x] = v;
    __syncthreads();
#pragma unroll
    for (int off = 1; off < 256; off <<= 1) {
        int tv = (threadIdx.x >= off) ? s[threadIdx.x - off] : 0;
        __syncthreads();
        s[threadIdx.x] += tv;
        __syncthreads();
    }
    if (i < NN) g_off[i] = s[threadIdx.x] - v;
    if (threadIdx.x == 255) g_bsum[blockIdx.x] = s[255];
}

__global__ void k_scan2() {
    __shared__ int s[256];
    int t = threadIdx.x;
    int v = (t < NBLK_SCAN) ? g_bsum[t] : 0;
    s[t] = v;
    __syncthreads();
#pragma unroll
    for (int off = 1; off < 256; off <<= 1) {
        int tv = (t >= off) ? s[t - off] : 0;
        __syncthreads();
        s[t] += tv;
        __syncthreads();
    }
    if (t < NBLK_SCAN) g_bsum[t] = s[t] - v;
}

__global__ void k_scatter(const int* __restrict__ src, const int* __restrict__ dst) {
    int e = blockIdx.x * blockDim.x + threadIdx.x;
    if (e >= EE) return;
    int d = dst[e];
    int pos = atomicAdd(&g_cur[d], 1);
    g_esrc[g_off[d] + g_bsum[d >> 8] + pos] = src[e];
}

// ---------------- fused: aggregate + proj + gate + blend ----------------
__global__ void __launch_bounds__(NTHR, 1) k_aggnode(
    const float* __restrict__ ctx, const float* __restrict__ bgat,
    const float* __restrict__ bp, const float* __restrict__ bg,
    float* __restrict__ out) {
    extern __shared__ __align__(16) unsigned short sm[];
    unsigned short* Ahi = sm;                      // hg (agg result), then hp
    unsigned short* Alo = sm + TILE_U16;
    unsigned short* Bt  = sm + 2 * TILE_U16;       // Wp -> Wg1 -> Wg2
    unsigned short* Chi = sm + 4 * TILE_U16;       // ctx split, persistent
    unsigned short* Clo = sm + 5 * TILE_U16;
    int tid = threadIdx.x, wid = tid >> 5, lane = tid & 31;
    int g = lane >> 2, t = lane & 3;
    long nodebase = (long)blockIdx.x * MTILE;
    int m0 = (wid >> 2) * 32, n0 = (wid & 3) * 32;

    // ctx tiles + Wp while agg runs below
    fill_A(Chi, Clo, ctx, nodebase, tid);
    copy_B(Bt, g_WpT, tid);

    // ---- agg phase: warp w handles nodes w*8 .. w*8+7 ----
    {
        int hd = lane >> 3;
        uint32_t* H = (uint32_t*)Ahi;
        uint32_t* L = (uint32_t*)Alo;
        float4 b4 = ((const float4*)bgat)[lane];
#pragma unroll
        for (int j = 0; j < 8; j++) {
            int r = wid * 8 + j;
            long node = nodebase + r;
            float4 acc = make_float4(0.f, 0.f, 0.f, 0.f);
            float dsum = 0.f;
            if (node < NN) {
                int beg = g_off[node] + g_bsum[node >> 8];
                int end = beg + g_cnt[node];
                float er_h = (lane < HH) ? g_er[node * HH + lane] : 0.f;
                float er16 = __shfl_sync(0xffffffffu, er_h, lane & 3);
                int i = beg;
                for (; i + 3 < end; i += 4) {
                    int s0 = __ldg(&g_esrc[i]);
                    int s1 = __ldg(&g_esrc[i + 1]);
                    int s2 = __ldg(&g_esrc[i + 2]);
                    int s3 = __ldg(&g_esrc[i + 3]);
                    float a = 0.f;
                    if (lane < 16) {
                        int eix = lane >> 2;
                        int sx = (eix == 0) ? s0 : (eix == 1) ? s1 : (eix == 2) ? s2 : s3;
                        float e = g_el[sx * HH + (lane & 3)] + er16;
                        e = (e > 0.f) ? e : NEG_SLOPE * e;
                        a = __expf(e);
                    }
                    float a0 = __shfl_sync(0xffffffffu, a, hd);
                    float a1 = __shfl_sync(0xffffffffu, a, 4 + hd);
                    float a2 = __shfl_sync(0xffffffffu, a, 8 + hd);
                    float a3 = __shfl_sync(0xffffffffu, a, 12 + hd);
                    dsum += (a0 + a1) + (a2 + a3);
                    float4 f0 = ((const float4*)g_feat)[(size_t)s0 * (IN_DIM / 4) + lane];
                    float4 f1 = ((const float4*)g_feat)[(size_t)s1 * (IN_DIM / 4) + lane];
                    float4 f2 = ((const float4*)g_feat)[(size_t)s2 * (IN_DIM / 4) + lane];
                    float4 f3 = ((const float4*)g_feat)[(size_t)s3 * (IN_DIM / 4) + lane];
                    acc.x = fmaf(f0.x, a0, acc.x); acc.y = fmaf(f0.y, a0, acc.y);
                    acc.z = fmaf(f0.z, a0, acc.z); acc.w = fmaf(f0.w, a0, acc.w);
                    acc.x = fmaf(f1.x, a1, acc.x); acc.y = fmaf(f1.y, a1, acc.y);
                    acc.z = fmaf(f1.z, a1, acc.z); acc.w = fmaf(f1.w, a1, acc.w);
                    acc.x = fmaf(f2.x, a2, acc.x); acc.y = fmaf(f2.y, a2, acc.y);
                    acc.z = fmaf(f2.z, a2, acc.z); acc.w = fmaf(f2.w, a2, acc.w);
                    acc.x = fmaf(f3.x, a3, acc.x); acc.y = fmaf(f3.y, a3, acc.y);
                    acc.z = fmaf(f3.z, a3, acc.z); acc.w = fmaf(f3.w, a3, acc.w);
                }
                for (; i < end; i++) {
                    int s0 = __ldg(&g_esrc[i]);
                    float a = 0.f;
                    if (lane < 4) {
                        float e = g_el[s0 * HH + lane] + er16;
                        e = (e > 0.f) ? e : NEG_SLOPE * e;
                        a = __expf(e);
                    }
                    float a0 = __shfl_sync(0xffffffffu, a, hd);
                    dsum += a0;
                    float4 f0 = ((const float4*)g_feat)[(size_t)s0 * (IN_DIM / 4) + lane];
                    acc.x = fmaf(f0.x, a0, acc.x); acc.y = fmaf(f0.y, a0, acc.y);
                    acc.z = fmaf(f0.z, a0, acc.z); acc.w = fmaf(f0.w, a0, acc.w);
                }
            }
            float inv = (dsum > 0.f) ? (1.f / dsum) : 0.f;
            float4 o;
            o.x = acc.x * inv + b4.x; o.y = acc.y * inv + b4.y;
            o.z = acc.z * inv + b4.z; o.w = acc.w * inv + b4.w;
            o.x = (o.x > 0.f) ? o.x : expm1f(o.x);
            o.y = (o.y > 0.f) ? o.y : expm1f(o.y);
            o.z = (o.z > 0.f) ? o.z : expm1f(o.z);
            o.w = (o.w > 0.f) ? o.w : expm1f(o.w);
            // split into A tiles at row r, cols 4*lane..4*lane+3
            uint32_t h01, l01, h23, l23;
            split2(o.x, o.y, h01, l01);
            split2(o.z, o.w, h23, l23);
            int idx = (r * TS + 4 * lane) >> 1;
            H[idx] = h01; H[idx + 1] = h23;
            L[idx] = l01; L[idx + 1] = l23;
        }
    }
    __syncthreads();

    // ---- phase 1: hp = hg @ Wp^T ----
    float acc[2][4][4];
#pragma unroll
    for (int a = 0; a < 2; a++)
#pragma unroll
        for (int b = 0; b < 4; b++)
#pragma unroll
            for (int c = 0; c < 4; c++) acc[a][b][c] = 0.f;

    gemm_tile<4>(acc, (const uint32_t*)Ahi, (const uint32_t*)Alo,
                 (const uint32_t*)Bt, (const uint32_t*)(Bt + TILE_U16), m0, n0, g, t);
    __syncthreads();

    // hp = acc + bias -> re-split into A tiles
    {
        uint32_t* H = (uint32_t*)Ahi;
        uint32_t* L = (uint32_t*)Alo;
#pragma unroll
        for (int nt = 0; nt < 4; nt++) {
            int col = n0 + nt * 8 + 2 * t;
            float2 bpv = *(const float2*)&bp[col];
#pragma unroll
            for (int mt = 0; mt < 2; mt++) {
                int r0 = m0 + mt * 16 + g, r1 = r0 + 8;
                float h0 = acc[mt][nt][0] + bpv.x, h1 = acc[mt][nt][1] + bpv.y;
                float h2 = acc[mt][nt][2] + bpv.x, h3 = acc[mt][nt][3] + bpv.y;
                uint32_t hi, lo;
                split2(h0, h1, hi, lo);
                H[(r0 * TS + col) >> 1] = hi;
                L[(r0 * TS + col) >> 1] = lo;
                split2(h2, h3, hi, lo);
                H[(r1 * TS + col) >> 1] = hi;
                L[(r1 * TS + col) >> 1] = lo;
            }
        }
    }
    copy_B(Bt, g_WgT, tid);
    __syncthreads();

    // ---- phase 2: gate = hp @ Wg1^T ----
#pragma unroll
    for (int a = 0; a < 2; a++)
#pragma unroll
        for (int b = 0; b < 4; b++)
#pragma unroll
            for (int c = 0; c < 4; c++) acc[a][b][c] = 0.f;
    gemm_tile<4>(acc, (const uint32_t*)Ahi, (const uint32_t*)Alo,
                 (const uint32_t*)Bt, (const uint32_t*)(Bt + TILE_U16), m0, n0, g, t);
    __syncthreads();

    // ---- phase 3: gate += ctx @ Wg2^T ----
    copy_B(Bt, g_WgT + 2 * TILE_U16, tid);
    __syncthreads();
    gemm_tile<4>(acc, (const uint32_t*)Chi, (const uint32_t*)Clo,
                 (const uint32_t*)Bt, (const uint32_t*)(Bt + TILE_U16), m0, n0, g, t);

    // ---- epilogue ----
#pragma unroll
    for (int nt = 0; nt < 4; nt++) {
        int col = n0 + nt * 8 + 2 * t;
        float2 bgv = *(const float2*)&bg[col];
#pragma unroll
        for (int mt = 0; mt < 2; mt++) {
            int lr0 = m0 + mt * 16 + g, lr1 = lr0 + 8;
            long r0 = nodebase + lr0, r1 = nodebase + lr1;
            if (r0 < NN) {
                float2 cv = recon2(Chi, Clo, lr0 * TS + col);
                float2 hv = recon2(Ahi, Alo, lr0 * TS + col);
                float s0 = 1.f / (1.f + __expf(-(acc[mt][nt][0] + bgv.x)));
                float s1 = 1.f / (1.f + __expf(-(acc[mt][nt][1] + bgv.y)));
                *(float2*)&out[r0 * IN_DIM + col] =
                    make_float2(s0 * hv.x + (1.f - s0) * cv.x, s1 * hv.y + (1.f - s1) * cv.y);
            }
            if (r1 < NN) {
                float2 cv = recon2(Chi, Clo, lr1 * TS + col);
                float2 hv = recon2(Ahi, Alo, lr1 * TS + col);
                float s2 = 1.f / (1.f + __expf(-(acc[mt][nt][2] + bgv.x)));
                float s3 = 1.f / (1.f + __expf(-(acc[mt][nt][3] + bgv.y)));
                *(float2*)&out[r1 * IN_DIM + col] =
                    make_float2(s2 * hv.x + (1.f - s2) * cv.x, s3 * hv.y + (1.f - s3) * cv.y);
            }
        }
    }
}

// ---------------- launch ----------------
#define SMEM_FEAT (4 * TILE_B)     // 139264
#define SMEM_NODE (6 * TILE_B)     // 208896

extern "C" void kernel_launch(void* const* d_in, const int* in_sizes, int n_in,
                              void* d_out, int out_size) {
    const float* h    = (const float*)d_in[0];
    const int*   src  = (const int*)d_in[1];
    const int*   dst  = (const int*)d_in[2];
    const float* ctx  = (const float*)d_in[3];
    const float* Wfc  = (const float*)d_in[4];
    const float* al   = (const float*)d_in[5];
    const float* ar   = (const float*)d_in[6];
    const float* bgat = (const float*)d_in[7];
    const float* Wp   = (const float*)d_in[8];
    const float* bp   = (const float*)d_in[9];
    const float* Wg   = (const float*)d_in[10];
    const float* bg   = (const float*)d_in[11];
    float* out = (float*)d_out;

    static int inited = 0;
    static cudaStream_t s1;
    static cudaEvent_t evA, evB;
    if (!inited) {
        cudaFuncSetAttribute(k_feat_tc, cudaFuncAttributeMaxDynamicSharedMemorySize, SMEM_FEAT);
        cudaFuncSetAttribute(k_aggnode, cudaFuncAttributeMaxDynamicSharedMemorySize, SMEM_NODE);
        cudaStreamCreateWithFlags(&s1, cudaStreamNonBlocking);
        cudaEventCreateWithFlags(&evA, cudaEventDisableTiming);
        cudaEventCreateWithFlags(&evB, cudaEventDisableTiming);
        inited = 1;
    }

    // fork: side stream does Wp/Wg prep + CSR build
    cudaEventRecord(evA, 0);
    cudaStreamWaitEvent(s1, evA, 0);
    k_prepw_pg<<<192, 256, 0, s1>>>(Wp, Wg);
    k_init<<<(NN + 255) / 256, 256, 0, s1>>>();
    k_hist<<<(EE + 255) / 256, 256, 0, s1>>>(dst);
    k_scan1<<<NBLK_SCAN, 256, 0, s1>>>();
    k_scan2<<<1, 256, 0, s1>>>();
    k_scatter<<<(EE + 255) / 256, 256, 0, s1>>>(src, dst);
    cudaEventRecord(evB, s1);

    // main: Wfc prep, feat, then fused agg+node
    k_prepw_fc<<<64, 256>>>(Wfc);
    k_feat_tc<<<NCTA_GEMM, NTHR, SMEM_FEAT>>>(h, al, ar);
    cudaStreamWaitEvent(0, evB, 0);
    k_aggnode<<<NCTA_GEMM, NTHR, SMEM_NODE>>>(ctx, bgat, bp, bg, out);
}

// round 13
// speedup vs baseline: 1.2338x; 1.2338x over previous
#include <cuda_runtime.h>
#include <cuda_bf16.h>
#include <math.h>
#include <stdint.h>

#define NN 50000
#define EE 800000
#define IN_DIM 128
#define HH 4
#define NEG_SLOPE 0.2f
#define NBLK_SCAN 196
#define MTILE 128
#define NCTA_GEMM 391
#define TS 136
#define TILE_U16 (128 * TS)
#define TILE_B (TILE_U16 * 2)
#define NTHR 512

// ---------------- scratch ----------------
__device__ float g_feat[(size_t)NN * IN_DIM];
__device__ float g_el[NN * HH];
__device__ float g_er[NN * HH];
__device__ float g_hg[(size_t)NN * IN_DIM];
__device__ float g_bfuse[IN_DIM];
__device__ int   g_cnt[NN];
__device__ int   g_off[NN];
__device__ int   g_cur[NN];
__device__ int   g_esrc[EE];
__device__ int   g_bsum[256];
__device__ __align__(16) unsigned short g_WfcT[2 * TILE_U16];
__device__ __align__(16) unsigned short g_WpT[2 * TILE_U16];
__device__ __align__(16) unsigned short g_WpgT[2 * TILE_U16];   // (Wp @ Wg1) transposed split
__device__ __align__(16) unsigned short g_WgT[4 * TILE_U16];

// ---------------- helpers ----------------
__device__ __forceinline__ unsigned short bfb(__nv_bfloat16 v) {
    return *reinterpret_cast<unsigned short*>(&v);
}
__device__ __forceinline__ void split2(float x0, float x1, uint32_t& hi, uint32_t& lo) {
    __nv_bfloat16 h0 = __float2bfloat16(x0), h1 = __float2bfloat16(x1);
    __nv_bfloat16 l0 = __float2bfloat16(x0 - __bfloat162float(h0));
    __nv_bfloat16 l1 = __float2bfloat16(x1 - __bfloat162float(h1));
    hi = (uint32_t)bfb(h0) | ((uint32_t)bfb(h1) << 16);
    lo = (uint32_t)bfb(l0) | ((uint32_t)bfb(l1) << 16);
}
__device__ __forceinline__ float2 recon2(const unsigned short* Hi, const unsigned short* Lo, int idx) {
    __nv_bfloat162 h = *(const __nv_bfloat162*)&Hi[idx];
    __nv_bfloat162 l = *(const __nv_bfloat162*)&Lo[idx];
    float2 hf = __bfloat1622float2(h);
    float2 lf = __bfloat1622float2(l);
    return make_float2(hf.x + lf.x, hf.y + lf.y);
}
__device__ __forceinline__ void hmma(float* c, uint32_t a0, uint32_t a1, uint32_t a2, uint32_t a3,
                                     uint32_t b0, uint32_t b1) {
    asm volatile(
        "mma.sync.aligned.m16n8k16.row.col.f32.bf16.bf16.f32 "
        "{%0,%1,%2,%3}, {%4,%5,%6,%7}, {%8,%9}, {%0,%1,%2,%3};"
        : "+f"(c[0]), "+f"(c[1]), "+f"(c[2]), "+f"(c[3])
        : "r"(a0), "r"(a1), "r"(a2), "r"(a3), "r"(b0), "r"(b1));
}

template <int NT>
__device__ __forceinline__ void gemm_tile(float acc[2][NT][4],
    const uint32_t* Ahi, const uint32_t* Alo,
    const uint32_t* Bhi, const uint32_t* Blo,
    int m0, int n0, int g, int t) {
#pragma unroll
    for (int ks = 0; ks < 8; ks++) {
        int k0 = ks * 16;
        uint32_t ah[2][4], al[2][4];
#pragma unroll
        for (int mt = 0; mt < 2; mt++) {
            int r = m0 + mt * 16 + g;
            int i0 = (r * TS + k0 + 2 * t) >> 1;
            int i1 = ((r + 8) * TS + k0 + 2 * t) >> 1;
            ah[mt][0] = Ahi[i0]; ah[mt][1] = Ahi[i1];
            ah[mt][2] = Ahi[i0 + 4]; ah[mt][3] = Ahi[i1 + 4];
            al[mt][0] = Alo[i0]; al[mt][1] = Alo[i1];
            al[mt][2] = Alo[i0 + 4]; al[mt][3] = Alo[i1 + 4];
        }
#pragma unroll
        for (int nt = 0; nt < NT; nt++) {
            int c = n0 + nt * 8 + g;
            int bi = (c * TS + k0 + 2 * t) >> 1;
            uint32_t bh0 = Bhi[bi], bh1 = Bhi[bi + 4];
            uint32_t bl0 = Blo[bi], bl1 = Blo[bi + 4];
#pragma unroll
            for (int mt = 0; mt < 2; mt++) {
                hmma(acc[mt][nt], ah[mt][0], ah[mt][1], ah[mt][2], ah[mt][3], bh0, bh1);
                hmma(acc[mt][nt], ah[mt][0], ah[mt][1], ah[mt][2], ah[mt][3], bl0, bl1);
                hmma(acc[mt][nt], al[mt][0], al[mt][1], al[mt][2], al[mt][3], bh0, bh1);
            }
        }
    }
}

__device__ __forceinline__ void fill_A(unsigned short* Ahi, unsigned short* Alo,
                                       const float* __restrict__ src, long nodebase,
                                       int tid) {
    int m = tid >> 2, q = tid & 3;
    long node = nodebase + m;
    const float* row = src + node * IN_DIM + q * 32;
    uint32_t* H = (uint32_t*)Ahi;
    uint32_t* L = (uint32_t*)Alo;
#pragma unroll
    for (int k4 = 0; k4 < 32; k4 += 4) {
        float4 v = make_float4(0.f, 0.f, 0.f, 0.f);
        if (node < NN) v = *(const float4*)(row + k4);
        uint32_t h01, l01, h23, l23;
        split2(v.x, v.y, h01, l01);
        split2(v.z, v.w, h23, l23);
        int idx = (m * TS + q * 32 + k4) >> 1;
        H[idx] = h01; H[idx + 1] = h23;
        L[idx] = l01; L[idx + 1] = l23;
    }
}

__device__ __forceinline__ void copy_B(unsigned short* dst, const unsigned short* src, int tid) {
    const uint4* s = (const uint4*)src;
    uint4* d = (uint4*)dst;
#pragma unroll
    for (int i = tid; i < 2 * TILE_B / 16; i += NTHR) d[i] = s[i];
}

// ---------------- small kernels ----------------
__global__ void k_init() {
    int i = blockIdx.x * blockDim.x + threadIdx.x;
    if (i < NN) { g_cnt[i] = 0; g_cur[i] = 0; }
}

__global__ void k_hist(const int* __restrict__ dst) {
    int e = blockIdx.x * blockDim.x + threadIdx.x;
    if (e < EE) atomicAdd(&g_cnt[dst[e]], 1);
}

__global__ void k_prepw_fc(const float* __restrict__ Wfc) {
    int id = blockIdx.x * 256 + threadIdx.x;
    if (id >= 16384) return;
    int n = id >> 7, k = id & 127;
    float w = Wfc[k * 128 + n];
    __nv_bfloat16 hi = __float2bfloat16(w);
    __nv_bfloat16 lo = __float2bfloat16(w - __bfloat162float(hi));
    g_WfcT[n * TS + k] = bfb(hi);
    g_WfcT[TILE_U16 + n * TS + k] = bfb(lo);
}

__global__ void k_prepw_pg(const float* __restrict__ Wp, const float* __restrict__ Wg) {
    int id = blockIdx.x * 256 + threadIdx.x;
    if (id < 16384) {
        int n = id >> 7, k = id & 127;
        float w = Wp[k * 128 + n];
        __nv_bfloat16 hi = __float2bfloat16(w);
        __nv_bfloat16 lo = __float2bfloat16(w - __bfloat162float(hi));
        g_WpT[n * TS + k] = bfb(hi);
        g_WpT[TILE_U16 + n * TS + k] = bfb(lo);
    } else if (id < 49152) {
        int e = id - 16384;
        int n = e & 127, k = e >> 7;
        float w = Wg[k * 128 + n];
        int stage = k >> 7, kk = k & 127;
        __nv_bfloat16 hi = __float2bfloat16(w);
        __nv_bfloat16 lo = __float2bfloat16(w - __bfloat162float(hi));
        g_WgT[stage * 2 * TILE_U16 + n * TS + kk] = bfb(hi);
        g_WgT[stage * 2 * TILE_U16 + TILE_U16 + n * TS + kk] = bfb(lo);
    }
}

// Wpg = Wp @ Wg1 (fp32), bfuse = bp @ Wg1 + bg
__global__ void k_prepmm(const float* __restrict__ Wp, const float* __restrict__ Wg,
                         const float* __restrict__ bp, const float* __restrict__ bg) {
    int id = blockIdx.x * 256 + threadIdx.x;   // 16384
    if (id < 16384) {
        int j = id >> 7, n = id & 127;         // Wpg[j][n] = sum_k Wp[j][k] * Wg[k][n]
        float s = 0.f;
#pragma unroll 4
        for (int k = 0; k < 128; k++)
            s = fmaf(__ldg(&Wp[j * 128 + k]), __ldg(&Wg[k * 128 + n]), s);
        __nv_bfloat16 hi = __float2bfloat16(s);
        __nv_bfloat16 lo = __float2bfloat16(s - __bfloat162float(hi));
        g_WpgT[n * TS + j] = bfb(hi);
        g_WpgT[TILE_U16 + n * TS + j] = bfb(lo);
    }
    if (blockIdx.x == 0 && threadIdx.x < 128) {
        int n = threadIdx.x;
        float s = __ldg(&bg[n]);
#pragma unroll 4
        for (int k = 0; k < 128; k++)
            s = fmaf(__ldg(&bp[k]), __ldg(&Wg[k * 128 + n]), s);
        g_bfuse[n] = s;
    }
}

// ---------------- feat = h @ W_fc, fused el/er ----------------
__global__ void __launch_bounds__(NTHR, 1) k_feat_tc(const float* __restrict__ h,
                                                     const float* __restrict__ al,
                                                     const float* __restrict__ ar) {
    extern __shared__ __align__(16) unsigned short sm[];
    unsigned short* Ahi = sm;
    unsigned short* Alo = sm + TILE_U16;
    unsigned short* Bt  = sm + 2 * TILE_U16;
    int tid = threadIdx.x, wid = tid >> 5, lane = tid & 31;
    int g = lane >> 2, t = lane & 3;
    long nodebase = (long)blockIdx.x * MTILE;

    fill_A(Ahi, Alo, h, nodebase, tid);
    copy_B(Bt, g_WfcT, tid);
    __syncthreads();

    float acc[2][4][4];
#pragma unroll
    for (int a = 0; a < 2; a++)
#pragma unroll
        for (int b = 0; b < 4; b++)
#pragma unroll
            for (int c = 0; c < 4; c++) acc[a][b][c] = 0.f;

    int m0 = (wid >> 2) * 32, n0 = (wid & 3) * 32;
    gemm_tile<4>(acc, (const uint32_t*)Ahi, (const uint32_t*)Alo,
                 (const uint32_t*)Bt, (const uint32_t*)(Bt + TILE_U16), m0, n0, g, t);

    int head = wid & 3;
    float pl[4] = {0.f, 0.f, 0.f, 0.f};
    float pr[4] = {0.f, 0.f, 0.f, 0.f};
#pragma unroll
    for (int nt = 0; nt < 4; nt++) {
        int col = n0 + nt * 8 + 2 * t;
        float a0 = __ldg(&al[col]), a1 = __ldg(&al[col + 1]);
        float b0 = __ldg(&ar[col]), b1 = __ldg(&ar[col + 1]);
#pragma unroll
        for (int mt = 0; mt < 2; mt++) {
            pl[2 * mt]     += acc[mt][nt][0] * a0 + acc[mt][nt][1] * a1;
            pl[2 * mt + 1] += acc[mt][nt][2] * a0 + acc[mt][nt][3] * a1;
            pr[2 * mt]     += acc[mt][nt][0] * b0 + acc[mt][nt][1] * b1;
            pr[2 * mt + 1] += acc[mt][nt][2] * b0 + acc[mt][nt][3] * b1;
        }
    }
#pragma unroll
    for (int off = 1; off <= 2; off <<= 1) {
#pragma unroll
        for (int i = 0; i < 4; i++) {
            pl[i] += __shfl_xor_sync(0xffffffffu, pl[i], off);
            pr[i] += __shfl_xor_sync(0xffffffffu, pr[i], off);
        }
    }
    if (t == 0) {
#pragma unroll
        for (int mt = 0; mt < 2; mt++) {
            long r0 = nodebase + m0 + mt * 16 + g;
            long r1 = r0 + 8;
            if (r0 < NN) { g_el[r0 * HH + head] = pl[2 * mt];     g_er[r0 * HH + head] = pr[2 * mt]; }
            if (r1 < NN) { g_el[r1 * HH + head] = pl[2 * mt + 1]; g_er[r1 * HH + head] = pr[2 * mt + 1]; }
        }
    }

#pragma unroll
    for (int mt = 0; mt < 2; mt++) {
        long r0 = nodebase + m0 + mt * 16 + g;
        long r1 = r0 + 8;
#pragma unroll
        for (int nt = 0; nt < 4; nt++) {
            int col = n0 + nt * 8 + 2 * t;
            if (r0 < NN) *(float2*)&g_feat[r0 * IN_DIM + col] = make_float2(acc[mt][nt][0], acc[mt][nt][1]);
            if (r1 < NN) *(float2*)&g_feat[r1 * IN_DIM + col] = make_float2(acc[mt][nt][2], acc[mt][nt][3]);
        }
    }
}

// ---------------- scans / scatter ----------------
__global__ void k_scan1() {
    __shared__ int s[256];
    int i = blockIdx.x * 256 + threadIdx.x;
    int v = (i < NN) ? g_cnt[i] : 0;
    s[threadIdx.x] = v;
    __syncthreads();
#pragma unroll
    for (int off = 1; off < 256; off <<= 1) {
        int tv = (threadIdx.x >= off) ? s[threadIdx.x - off] : 0;
        __syncthreads();
        s[threadIdx.x] += tv;
        __syncthreads();
    }
    if (i < NN) g_off[i] = s[threadIdx.x] - v;
    if (threadIdx.x == 255) g_bsum[blockIdx.x] = s[255];
}

__global__ void k_scan2() {
    __shared__ int s[256];
    int t = threadIdx.x;
    int v = (t < NBLK_SCAN) ? g_bsum[t] : 0;
    s[t] = v;
    __syncthreads();
#pragma unroll
    for (int off = 1; off < 256; off <<= 1) {
        int tv = (t >= off) ? s[t - off] : 0;
        __syncthreads();
        s[t] += tv;
        __syncthreads();
    }
    if (t < NBLK_SCAN) g_bsum[t] = s[t] - v;
}

__global__ void k_scatter(const int* __restrict__ src, const int* __restrict__ dst) {
    int e = blockIdx.x * blockDim.x + threadIdx.x;
    if (e >= EE) return;
    int d = dst[e];
    int pos = atomicAdd(&g_cur[d], 1);
    g_esrc[g_off[d] + g_bsum[d >> 8] + pos] = src[e];
}

// ---------------- aggregate: warp per node, 4 edges/iter ----------------
__global__ void k_agg(const float* __restrict__ bgat) {
    int gw = (blockIdx.x * blockDim.x + threadIdx.x) >> 5;
    if (gw >= NN) return;
    int lane = threadIdx.x & 31;
    int beg = g_off[gw] + g_bsum[gw >> 8];
    int end = beg + g_cnt[gw];
    float er_h = (lane < HH) ? g_er[gw * HH + lane] : 0.f;
    float er16 = __shfl_sync(0xffffffffu, er_h, lane & 3);
    int hd = lane >> 3;
    float4 acc = make_float4(0.f, 0.f, 0.f, 0.f);
    float dsum = 0.f;
    int i = beg;
    for (; i + 3 < end; i += 4) {
        int s0 = __ldg(&g_esrc[i]);
        int s1 = __ldg(&g_esrc[i + 1]);
        int s2 = __ldg(&g_esrc[i + 2]);
        int s3 = __ldg(&g_esrc[i + 3]);
        float a = 0.f;
        if (lane < 16) {
            int eix = lane >> 2;
            int sx = (eix == 0) ? s0 : (eix == 1) ? s1 : (eix == 2) ? s2 : s3;
            float e = g_el[sx * HH + (lane & 3)] + er16;
            e = (e > 0.f) ? e : NEG_SLOPE * e;
            a = __expf(e);
        }
        float a0 = __shfl_sync(0xffffffffu, a, hd);
        float a1 = __shfl_sync(0xffffffffu, a, 4 + hd);
        float a2 = __shfl_sync(0xffffffffu, a, 8 + hd);
        float a3 = __shfl_sync(0xffffffffu, a, 12 + hd);
        dsum += (a0 + a1) + (a2 + a3);
        float4 f0 = ((const float4*)g_feat)[(size_t)s0 * (IN_DIM / 4) + lane];
        float4 f1 = ((const float4*)g_feat)[(size_t)s1 * (IN_DIM / 4) + lane];
        float4 f2 = ((const float4*)g_feat)[(size_t)s2 * (IN_DIM / 4) + lane];
        float4 f3 = ((const float4*)g_feat)[(size_t)s3 * (IN_DIM / 4) + lane];
        acc.x = fmaf(f0.x, a0, acc.x); acc.y = fmaf(f0.y, a0, acc.y);
        acc.z = fmaf(f0.z, a0, acc.z); acc.w = fmaf(f0.w, a0, acc.w);
        acc.x = fmaf(f1.x, a1, acc.x); acc.y = fmaf(f1.y, a1, acc.y);
        acc.z = fmaf(f1.z, a1, acc.z); acc.w = fmaf(f1.w, a1, acc.w);
        acc.x = fmaf(f2.x, a2, acc.x); acc.y = fmaf(f2.y, a2, acc.y);
        acc.z = fmaf(f2.z, a2, acc.z); acc.w = fmaf(f2.w, a2, acc.w);
        acc.x = fmaf(f3.x, a3, acc.x); acc.y = fmaf(f3.y, a3, acc.y);
        acc.z = fmaf(f3.z, a3, acc.z); acc.w = fmaf(f3.w, a3, acc.w);
    }
    for (; i < end; i++) {
        int s0 = __ldg(&g_esrc[i]);
        float a = 0.f;
        if (lane < 4) {
            float e = g_el[s0 * HH + lane] + er16;
            e = (e > 0.f) ? e : NEG_SLOPE * e;
            a = __expf(e);
        }
        float a0 = __shfl_sync(0xffffffffu, a, hd);
        dsum += a0;
        float4 f0 = ((const float4*)g_feat)[(size_t)s0 * (IN_DIM / 4) + lane];
        acc.x = fmaf(f0.x, a0, acc.x); acc.y = fmaf(f0.y, a0, acc.y);
        acc.z = fmaf(f0.z, a0, acc.z); acc.w = fmaf(f0.w, a0, acc.w);
    }
    float inv = (dsum > 0.f) ? (1.f / dsum) : 0.f;
    float4 b = ((const float4*)bgat)[lane];
    float4 o;
    o.x = acc.x * inv + b.x; o.y = acc.y * inv + b.y;
    o.z = acc.z * inv + b.z; o.w = acc.w * inv + b.w;
    o.x = (o.x > 0.f) ? o.x : expm1f(o.x);
    o.y = (o.y > 0.f) ? o.y : expm1f(o.y);
    o.z = (o.z > 0.f) ? o.z : expm1f(o.z);
    o.w = (o.w > 0.f) ? o.w : expm1f(o.w);
    ((float4*)g_hg)[(size_t)gw * (IN_DIM / 4) + lane] = o;
}

// ---------------- node: proj + gate + blend (fused-weight form) ----------
__global__ void __launch_bounds__(NTHR, 1) k_node_tc(
    const float* __restrict__ ctx, const float* __restrict__ bp,
    float* __restrict__ out) {
    extern __shared__ __align__(16) unsigned short sm[];
    unsigned short* Ahi = sm;                      // hg split, persistent
    unsigned short* Alo = sm + TILE_U16;
    unsigned short* Bt  = sm + 2 * TILE_U16;       // Wp -> Wpg -> Wg2
    unsigned short* Chi = sm + 4 * TILE_U16;       // ctx split, persistent
    unsigned short* Clo = sm + 5 * TILE_U16;
    int tid = threadIdx.x, wid = tid >> 5, lane = tid & 31;
    int g = lane >> 2, t = lane & 3;
    long nodebase = (long)blockIdx.x * MTILE;
    int m0 = (wid >> 2) * 32, n0 = (wid & 3) * 32;

    fill_A(Ahi, Alo, g_hg, nodebase, tid);
    fill_A(Chi, Clo, ctx, nodebase, tid);
    copy_B(Bt, g_WpT, tid);
    __syncthreads();

    // GEMM1: hp(no bias) = hg @ Wp^T
    float pacc[2][4][4];
#pragma unroll
    for (int a = 0; a < 2; a++)
#pragma unroll
        for (int b = 0; b < 4; b++)
#pragma unroll
            for (int c = 0; c < 4; c++) pacc[a][b][c] = 0.f;
    gemm_tile<4>(pacc, (const uint32_t*)Ahi, (const uint32_t*)Alo,
                 (const uint32_t*)Bt, (const uint32_t*)(Bt + TILE_U16), m0, n0, g, t);
    __syncthreads();

    // GEMM2: gate = hg @ Wpg^T  (same A tiles!)
    copy_B(Bt, g_WpgT, tid);
    __syncthreads();
    float gacc[2][4][4];
#pragma unroll
    for (int a = 0; a < 2; a++)
#pragma unroll
        for (int b = 0; b < 4; b++)
#pragma unroll
            for (int c = 0; c < 4; c++) gacc[a][b][c] = 0.f;
    gemm_tile<4>(gacc, (const uint32_t*)Ahi, (const uint32_t*)Alo,
                 (const uint32_t*)Bt, (const uint32_t*)(Bt + TILE_U16), m0, n0, g, t);
    __syncthreads();

    // GEMM3: gate += ctx @ Wg2^T
    copy_B(Bt, g_WgT + 2 * TILE_U16, tid);
    __syncthreads();
    gemm_tile<4>(gacc, (const uint32_t*)Chi, (const uint32_t*)Clo,
                 (const uint32_t*)Bt, (const uint32_t*)(Bt + TILE_U16), m0, n0, g, t);

    // epilogue: hp = pacc + bp (exact fp32), gate = sigmoid(gacc + bfuse)
#pragma unroll
    for (int nt = 0; nt < 4; nt++) {
        int col = n0 + nt * 8 + 2 * t;
        float2 bpv = *(const float2*)&bp[col];
        float2 bfv = *(const float2*)&g_bfuse[col];
#pragma unroll
        for (int mt = 0; mt < 2; mt++) {
            int lr0 = m0 + mt * 16 + g, lr1 = lr0 + 8;
            long r0 = nodebase + lr0, r1 = nodebase + lr1;
            if (r0 < NN) {
                float2 cv = recon2(Chi, Clo, lr0 * TS + col);
                float h0 = pacc[mt][nt][0] + bpv.x, h1 = pacc[mt][nt][1] + bpv.y;
                float s0 = 1.f / (1.f + __expf(-(gacc[mt][nt][0] + bfv.x)));
                float s1 = 1.f / (1.f + __expf(-(gacc[mt][nt][1] + bfv.y)));
                *(float2*)&out[r0 * IN_DIM + col] =
                    make_float2(s0 * h0 + (1.f - s0) * cv.x, s1 * h1 + (1.f - s1) * cv.y);
            }
            if (r1 < NN) {
                float2 cv = recon2(Chi, Clo, lr1 * TS + col);
                float h2 = pacc[mt][nt][2] + bpv.x, h3 = pacc[mt][nt][3] + bpv.y;
                float s2 = 1.f / (1.f + __expf(-(gacc[mt][nt][2] + bfv.x)));
                float s3 = 1.f / (1.f + __expf(-(gacc[mt][nt][3] + bfv.y)));
                *(float2*)&out[r1 * IN_DIM + col] =
                    make_float2(s2 * h2 + (1.f - s2) * cv.x, s3 * h3 + (1.f - s3) * cv.y);
            }
        }
    }
}

// ---------------- launch ----------------
#define SMEM_FEAT (4 * TILE_B)     // 139264
#define SMEM_NODE (6 * TILE_B)     // 208896

extern "C" void kernel_launch(void* const* d_in, const int* in_sizes, int n_in,
                              void* d_out, int out_size) {
    const float* h    = (const float*)d_in[0];
    const int*   src  = (const int*)d_in[1];
    const int*   dst  = (const int*)d_in[2];
    const float* ctx  = (const float*)d_in[3];
    const float* Wfc  = (const float*)d_in[4];
    const float* al   = (const float*)d_in[5];
    const float* ar   = (const float*)d_in[6];
    const float* bgat = (const float*)d_in[7];
    const float* Wp   = (const float*)d_in[8];
    const float* bp   = (const float*)d_in[9];
    const float* Wg   = (const float*)d_in[10];
    const float* bg   = (const float*)d_in[11];
    float* out = (float*)d_out;

    static int inited = 0;
    static cudaStream_t s1;
    static cudaEvent_t evA, evB, evD;
    if (!inited) {
        cudaFuncSetAttribute(k_feat_tc, cudaFuncAttributeMaxDynamicSharedMemorySize, SMEM_FEAT);
        cudaFuncSetAttribute(k_node_tc, cudaFuncAttributeMaxDynamicSharedMemorySize, SMEM_NODE);
        cudaStreamCreateWithFlags(&s1, cudaStreamNonBlocking);
        cudaEventCreateWithFlags(&evA, cudaEventDisableTiming);
        cudaEventCreateWithFlags(&evB, cudaEventDisableTiming);
        cudaEventCreateWithFlags(&evD, cudaEventDisableTiming);
        inited = 1;
    }

    // fork: side stream = CSR build first (agg join early), then weight preps
    cudaEventRecord(evA, 0);
    cudaStreamWaitEvent(s1, evA, 0);
    k_init<<<(NN + 255) / 256, 256, 0, s1>>>();
    k_hist<<<(EE + 255) / 256, 256, 0, s1>>>(dst);
    k_scan1<<<NBLK_SCAN, 256, 0, s1>>>();
    k_scan2<<<1, 256, 0, s1>>>();
    k_scatter<<<(EE + 255) / 256, 256, 0, s1>>>(src, dst);
    cudaEventRecord(evB, s1);
    k_prepw_pg<<<192, 256, 0, s1>>>(Wp, Wg);
    k_prepmm<<<64, 256, 0, s1>>>(Wp, Wg, bp, bg);
    cudaEventRecord(evD, s1);

    // main: Wfc prep, feat
    k_prepw_fc<<<64, 256>>>(Wfc);
    k_feat_tc<<<NCTA_GEMM, NTHR, SMEM_FEAT>>>(h, al, ar);

    // join, aggregate, node
    cudaStreamWaitEvent(0, evB, 0);
    k_agg<<<(NN * 32 + 255) / 256, 256>>>(bgat);
    cudaStreamWaitEvent(0, evD, 0);
    k_node_tc<<<NCTA_GEMM, NTHR, SMEM_NODE>>>(ctx, bp, out);
}

// round 14
// speedup vs baseline: 1.2579x; 1.0195x over previous
#include <cuda_runtime.h>
#include <cuda_bf16.h>
#include <math.h>
#include <stdint.h>

#define NN 50000
#define EE 800000
#define IN_DIM 128
#define HH 4
#define NEG_SLOPE 0.2f
#define NBLK_SCAN 196
#define MTILE 128
#define NCTA_GEMM 391
#define TS 136
#define TILE_U16 (128 * TS)
#define TILE_B (TILE_U16 * 2)
#define NTHR 512

// ---------------- scratch ----------------
__device__ float g_feat[(size_t)NN * IN_DIM];
__device__ float g_el[NN * HH];
__device__ float g_er[NN * HH];
__device__ float g_hg[(size_t)NN * IN_DIM];
__device__ float g_bfuse[IN_DIM];
__device__ int   g_cnt[NN];
__device__ int   g_off[NN];
__device__ int   g_cur[NN];
__device__ int   g_esrc[EE];
__device__ int   g_bsum[256];
__device__ __align__(16) unsigned short g_WfcT[2 * TILE_U16];
__device__ __align__(16) unsigned short g_WpT[2 * TILE_U16];
__device__ __align__(16) unsigned short g_WpgT[2 * TILE_U16];
__device__ __align__(16) unsigned short g_WgT[4 * TILE_U16];

// ---------------- helpers ----------------
__device__ __forceinline__ unsigned short bfb(__nv_bfloat16 v) {
    return *reinterpret_cast<unsigned short*>(&v);
}
__device__ __forceinline__ void split2(float x0, float x1, uint32_t& hi, uint32_t& lo) {
    __nv_bfloat16 h0 = __float2bfloat16(x0), h1 = __float2bfloat16(x1);
    __nv_bfloat16 l0 = __float2bfloat16(x0 - __bfloat162float(h0));
    __nv_bfloat16 l1 = __float2bfloat16(x1 - __bfloat162float(h1));
    hi = (uint32_t)bfb(h0) | ((uint32_t)bfb(h1) << 16);
    lo = (uint32_t)bfb(l0) | ((uint32_t)bfb(l1) << 16);
}
__device__ __forceinline__ float2 recon2(const unsigned short* Hi, const unsigned short* Lo, int idx) {
    __nv_bfloat162 h = *(const __nv_bfloat162*)&Hi[idx];
    __nv_bfloat162 l = *(const __nv_bfloat162*)&Lo[idx];
    float2 hf = __bfloat1622float2(h);
    float2 lf = __bfloat1622float2(l);
    return make_float2(hf.x + lf.x, hf.y + lf.y);
}
__device__ __forceinline__ void hmma(float* c, uint32_t a0, uint32_t a1, uint32_t a2, uint32_t a3,
                                     uint32_t b0, uint32_t b1) {
    asm volatile(
        "mma.sync.aligned.m16n8k16.row.col.f32.bf16.bf16.f32 "
        "{%0,%1,%2,%3}, {%4,%5,%6,%7}, {%8,%9}, {%0,%1,%2,%3};"
        : "+f"(c[0]), "+f"(c[1]), "+f"(c[2]), "+f"(c[3])
        : "r"(a0), "r"(a1), "r"(a2), "r"(a3), "r"(b0), "r"(b1));
}

template <int NT>
__device__ __forceinline__ void gemm_tile(float acc[2][NT][4],
    const uint32_t* Ahi, const uint32_t* Alo,
    const uint32_t* Bhi, const uint32_t* Blo,
    int m0, int n0, int g, int t) {
#pragma unroll
    for (int ks = 0; ks < 8; ks++) {
        int k0 = ks * 16;
        uint32_t ah[2][4], al[2][4];
#pragma unroll
        for (int mt = 0; mt < 2; mt++) {
            int r = m0 + mt * 16 + g;
            int i0 = (r * TS + k0 + 2 * t) >> 1;
            int i1 = ((r + 8) * TS + k0 + 2 * t) >> 1;
            ah[mt][0] = Ahi[i0]; ah[mt][1] = Ahi[i1];
            ah[mt][2] = Ahi[i0 + 4]; ah[mt][3] = Ahi[i1 + 4];
            al[mt][0] = Alo[i0]; al[mt][1] = Alo[i1];
            al[mt][2] = Alo[i0 + 4]; al[mt][3] = Alo[i1 + 4];
        }
#pragma unroll
        for (int nt = 0; nt < NT; nt++) {
            int c = n0 + nt * 8 + g;
            int bi = (c * TS + k0 + 2 * t) >> 1;
            uint32_t bh0 = Bhi[bi], bh1 = Bhi[bi + 4];
            uint32_t bl0 = Blo[bi], bl1 = Blo[bi + 4];
#pragma unroll
            for (int mt = 0; mt < 2; mt++) {
                hmma(acc[mt][nt], ah[mt][0], ah[mt][1], ah[mt][2], ah[mt][3], bh0, bh1);
                hmma(acc[mt][nt], ah[mt][0], ah[mt][1], ah[mt][2], ah[mt][3], bl0, bl1);
                hmma(acc[mt][nt], al[mt][0], al[mt][1], al[mt][2], al[mt][3], bh0, bh1);
            }
        }
    }
}

__device__ __forceinline__ void fill_A(unsigned short* Ahi, unsigned short* Alo,
                                       const float* __restrict__ src, long nodebase,
                                       int tid) {
    int m = tid >> 2, q = tid & 3;
    long node = nodebase + m;
    const float* row = src + node * IN_DIM + q * 32;
    uint32_t* H = (uint32_t*)Ahi;
    uint32_t* L = (uint32_t*)Alo;
#pragma unroll
    for (int k4 = 0; k4 < 32; k4 += 4) {
        float4 v = make_float4(0.f, 0.f, 0.f, 0.f);
        if (node < NN) v = *(const float4*)(row + k4);
        uint32_t h01, l01, h23, l23;
        split2(v.x, v.y, h01, l01);
        split2(v.z, v.w, h23, l23);
        int idx = (m * TS + q * 32 + k4) >> 1;
        H[idx] = h01; H[idx + 1] = h23;
        L[idx] = l01; L[idx + 1] = l23;
    }
}

__device__ __forceinline__ void copy_B(unsigned short* dst, const unsigned short* src, int tid) {
    const uint4* s = (const uint4*)src;
    uint4* d = (uint4*)dst;
#pragma unroll
    for (int i = tid; i < 2 * TILE_B / 16; i += NTHR) d[i] = s[i];
}

// ---------------- small kernels ----------------
__global__ void k_init() {
    int i = blockIdx.x * blockDim.x + threadIdx.x;
    if (i < NN) { g_cnt[i] = 0; g_cur[i] = 0; }
}

__global__ void k_hist(const int* __restrict__ dst) {
    int e = blockIdx.x * blockDim.x + threadIdx.x;
    if (e < EE) atomicAdd(&g_cnt[dst[e]], 1);
}

__global__ void k_prepw_fc(const float* __restrict__ Wfc) {
    int id = blockIdx.x * 256 + threadIdx.x;
    if (id >= 16384) return;
    int n = id >> 7, k = id & 127;
    float w = Wfc[k * 128 + n];
    __nv_bfloat16 hi = __float2bfloat16(w);
    __nv_bfloat16 lo = __float2bfloat16(w - __bfloat162float(hi));
    g_WfcT[n * TS + k] = bfb(hi);
    g_WfcT[TILE_U16 + n * TS + k] = bfb(lo);
}

__global__ void k_prepw_pg(const float* __restrict__ Wp, const float* __restrict__ Wg) {
    int id = blockIdx.x * 256 + threadIdx.x;
    if (id < 16384) {
        int n = id >> 7, k = id & 127;
        float w = Wp[k * 128 + n];
        __nv_bfloat16 hi = __float2bfloat16(w);
        __nv_bfloat16 lo = __float2bfloat16(w - __bfloat162float(hi));
        g_WpT[n * TS + k] = bfb(hi);
        g_WpT[TILE_U16 + n * TS + k] = bfb(lo);
    } else if (id < 49152) {
        int e = id - 16384;
        int n = e & 127, k = e >> 7;
        float w = Wg[k * 128 + n];
        int stage = k >> 7, kk = k & 127;
        __nv_bfloat16 hi = __float2bfloat16(w);
        __nv_bfloat16 lo = __float2bfloat16(w - __bfloat162float(hi));
        g_WgT[stage * 2 * TILE_U16 + n * TS + kk] = bfb(hi);
        g_WgT[stage * 2 * TILE_U16 + TILE_U16 + n * TS + kk] = bfb(lo);
    }
}

// Wpg = Wp @ Wg1 (fp32), bfuse = bp @ Wg1 + bg
__global__ void k_prepmm(const float* __restrict__ Wp, const float* __restrict__ Wg,
                         const float* __restrict__ bp, const float* __restrict__ bg) {
    int id = blockIdx.x * 256 + threadIdx.x;   // 16384
    if (id < 16384) {
        int j = id >> 7, n = id & 127;
        float s = 0.f;
#pragma unroll 4
        for (int k = 0; k < 128; k++)
            s = fmaf(__ldg(&Wp[j * 128 + k]), __ldg(&Wg[k * 128 + n]), s);
        __nv_bfloat16 hi = __float2bfloat16(s);
        __nv_bfloat16 lo = __float2bfloat16(s - __bfloat162float(hi));
        g_WpgT[n * TS + j] = bfb(hi);
        g_WpgT[TILE_U16 + n * TS + j] = bfb(lo);
    }
    if (blockIdx.x == 0 && threadIdx.x < 128) {
        int n = threadIdx.x;
        float s = __ldg(&bg[n]);
#pragma unroll 4
        for (int k = 0; k < 128; k++)
            s = fmaf(__ldg(&bp[k]), __ldg(&Wg[k * 128 + n]), s);
        g_bfuse[n] = s;
    }
}

// ---------------- feat = h @ W_fc, fused el/er ----------------
__global__ void __launch_bounds__(NTHR, 1) k_feat_tc(const float* __restrict__ h,
                                                     const float* __restrict__ al,
                                                     const float* __restrict__ ar) {
    extern __shared__ __align__(16) unsigned short sm[];
    unsigned short* Ahi = sm;
    unsigned short* Alo = sm + TILE_U16;
    unsigned short* Bt  = sm + 2 * TILE_U16;
    int tid = threadIdx.x, wid = tid >> 5, lane = tid & 31;
    int g = lane >> 2, t = lane & 3;
    long nodebase = (long)blockIdx.x * MTILE;

    fill_A(Ahi, Alo, h, nodebase, tid);
    copy_B(Bt, g_WfcT, tid);
    __syncthreads();

    float acc[2][4][4];
#pragma unroll
    for (int a = 0; a < 2; a++)
#pragma unroll
        for (int b = 0; b < 4; b++)
#pragma unroll
            for (int c = 0; c < 4; c++) acc[a][b][c] = 0.f;

    int m0 = (wid >> 2) * 32, n0 = (wid & 3) * 32;
    gemm_tile<4>(acc, (const uint32_t*)Ahi, (const uint32_t*)Alo,
                 (const uint32_t*)Bt, (const uint32_t*)(Bt + TILE_U16), m0, n0, g, t);

    int head = wid & 3;
    float pl[4] = {0.f, 0.f, 0.f, 0.f};
    float pr[4] = {0.f, 0.f, 0.f, 0.f};
#pragma unroll
    for (int nt = 0; nt < 4; nt++) {
        int col = n0 + nt * 8 + 2 * t;
        float a0 = __ldg(&al[col]), a1 = __ldg(&al[col + 1]);
        float b0 = __ldg(&ar[col]), b1 = __ldg(&ar[col + 1]);
#pragma unroll
        for (int mt = 0; mt < 2; mt++) {
            pl[2 * mt]     += acc[mt][nt][0] * a0 + acc[mt][nt][1] * a1;
            pl[2 * mt + 1] += acc[mt][nt][2] * a0 + acc[mt][nt][3] * a1;
            pr[2 * mt]     += acc[mt][nt][0] * b0 + acc[mt][nt][1] * b1;
            pr[2 * mt + 1] += acc[mt][nt][2] * b0 + acc[mt][nt][3] * b1;
        }
    }
#pragma unroll
    for (int off = 1; off <= 2; off <<= 1) {
#pragma unroll
        for (int i = 0; i < 4; i++) {
            pl[i] += __shfl_xor_sync(0xffffffffu, pl[i], off);
            pr[i] += __shfl_xor_sync(0xffffffffu, pr[i], off);
        }
    }
    if (t == 0) {
#pragma unroll
        for (int mt = 0; mt < 2; mt++) {
            long r0 = nodebase + m0 + mt * 16 + g;
            long r1 = r0 + 8;
            if (r0 < NN) { g_el[r0 * HH + head] = pl[2 * mt];     g_er[r0 * HH + head] = pr[2 * mt]; }
            if (r1 < NN) { g_el[r1 * HH + head] = pl[2 * mt + 1]; g_er[r1 * HH + head] = pr[2 * mt + 1]; }
        }
    }

#pragma unroll
    for (int mt = 0; mt < 2; mt++) {
        long r0 = nodebase + m0 + mt * 16 + g;
        long r1 = r0 + 8;
#pragma unroll
        for (int nt = 0; nt < 4; nt++) {
            int col = n0 + nt * 8 + 2 * t;
            if (r0 < NN) *(float2*)&g_feat[r0 * IN_DIM + col] = make_float2(acc[mt][nt][0], acc[mt][nt][1]);
            if (r1 < NN) *(float2*)&g_feat[r1 * IN_DIM + col] = make_float2(acc[mt][nt][2], acc[mt][nt][3]);
        }
    }
}

// ---------------- scans / scatter ----------------
__global__ void k_scan1() {
    __shared__ int s[256];
    int i = blockIdx.x * 256 + threadIdx.x;
    int v = (i < NN) ? g_cnt[i] : 0;
    s[threadIdx.x] = v;
    __syncthreads();
#pragma unroll
    for (int off = 1; off < 256; off <<= 1) {
        int tv = (threadIdx.x >= off) ? s[threadIdx.x - off] : 0;
        __syncthreads();
        s[threadIdx.x] += tv;
        __syncthreads();
    }
    if (i < NN) g_off[i] = s[threadIdx.x] - v;
    if (threadIdx.x == 255) g_bsum[blockIdx.x] = s[255];
}

__global__ void k_scan2() {
    __shared__ int s[256];
    int t = threadIdx.x;
    int v = (t < NBLK_SCAN) ? g_bsum[t] : 0;
    s[t] = v;
    __syncthreads();
#pragma unroll
    for (int off = 1; off < 256; off <<= 1) {
        int tv = (t >= off) ? s[t - off] : 0;
        __syncthreads();
        s[t] += tv;
        __syncthreads();
    }
    if (t < NBLK_SCAN) g_bsum[t] = s[t] - v;
}

__global__ void k_scatter(const int* __restrict__ src, const int* __restrict__ dst) {
    int e = blockIdx.x * blockDim.x + threadIdx.x;
    if (e >= EE) return;
    int d = dst[e];
    int pos = atomicAdd(&g_cur[d], 1);
    g_esrc[g_off[d] + g_bsum[d >> 8] + pos] = src[e];
}

// ---------------- aggregate: warp per node, 4 edges/iter ----------------
__global__ void k_agg(const float* __restrict__ bgat) {
    int gw = (blockIdx.x * blockDim.x + threadIdx.x) >> 5;
    if (gw >= NN) return;
    int lane = threadIdx.x & 31;
    int beg = g_off[gw] + g_bsum[gw >> 8];
    int end = beg + g_cnt[gw];
    float er_h = (lane < HH) ? g_er[gw * HH + lane] : 0.f;
    float er16 = __shfl_sync(0xffffffffu, er_h, lane & 3);
    int hd = lane >> 3;
    float4 acc = make_float4(0.f, 0.f, 0.f, 0.f);
    float dsum = 0.f;
    int i = beg;
    for (; i + 3 < end; i += 4) {
        int s0 = __ldg(&g_esrc[i]);
        int s1 = __ldg(&g_esrc[i + 1]);
        int s2 = __ldg(&g_esrc[i + 2]);
        int s3 = __ldg(&g_esrc[i + 3]);
        float a = 0.f;
        if (lane < 16) {
            int eix = lane >> 2;
            int sx = (eix == 0) ? s0 : (eix == 1) ? s1 : (eix == 2) ? s2 : s3;
            float e = g_el[sx * HH + (lane & 3)] + er16;
            e = (e > 0.f) ? e : NEG_SLOPE * e;
            a = __expf(e);
        }
        float a0 = __shfl_sync(0xffffffffu, a, hd);
        float a1 = __shfl_sync(0xffffffffu, a, 4 + hd);
        float a2 = __shfl_sync(0xffffffffu, a, 8 + hd);
        float a3 = __shfl_sync(0xffffffffu, a, 12 + hd);
        dsum += (a0 + a1) + (a2 + a3);
        float4 f0 = ((const float4*)g_feat)[(size_t)s0 * (IN_DIM / 4) + lane];
        float4 f1 = ((const float4*)g_feat)[(size_t)s1 * (IN_DIM / 4) + lane];
        float4 f2 = ((const float4*)g_feat)[(size_t)s2 * (IN_DIM / 4) + lane];
        float4 f3 = ((const float4*)g_feat)[(size_t)s3 * (IN_DIM / 4) + lane];
        acc.x = fmaf(f0.x, a0, acc.x); acc.y = fmaf(f0.y, a0, acc.y);
        acc.z = fmaf(f0.z, a0, acc.z); acc.w = fmaf(f0.w, a0, acc.w);
        acc.x = fmaf(f1.x, a1, acc.x); acc.y = fmaf(f1.y, a1, acc.y);
        acc.z = fmaf(f1.z, a1, acc.z); acc.w = fmaf(f1.w, a1, acc.w);
        acc.x = fmaf(f2.x, a2, acc.x); acc.y = fmaf(f2.y, a2, acc.y);
        acc.z = fmaf(f2.z, a2, acc.z); acc.w = fmaf(f2.w, a2, acc.w);
        acc.x = fmaf(f3.x, a3, acc.x); acc.y = fmaf(f3.y, a3, acc.y);
        acc.z = fmaf(f3.z, a3, acc.z); acc.w = fmaf(f3.w, a3, acc.w);
    }
    for (; i < end; i++) {
        int s0 = __ldg(&g_esrc[i]);
        float a = 0.f;
        if (lane < 4) {
            float e = g_el[s0 * HH + lane] + er16;
            e = (e > 0.f) ? e : NEG_SLOPE * e;
            a = __expf(e);
        }
        float a0 = __shfl_sync(0xffffffffu, a, hd);
        dsum += a0;
        float4 f0 = ((const float4*)g_feat)[(size_t)s0 * (IN_DIM / 4) + lane];
        acc.x = fmaf(f0.x, a0, acc.x); acc.y = fmaf(f0.y, a0, acc.y);
        acc.z = fmaf(f0.z, a0, acc.z); acc.w = fmaf(f0.w, a0, acc.w);
    }
    float inv = (dsum > 0.f) ? (1.f / dsum) : 0.f;
    float4 b = ((const float4*)bgat)[lane];
    float4 o;
    o.x = acc.x * inv + b.x; o.y = acc.y * inv + b.y;
    o.z = acc.z * inv + b.z; o.w = acc.w * inv + b.w;
    o.x = (o.x > 0.f) ? o.x : expm1f(o.x);
    o.y = (o.y > 0.f) ? o.y : expm1f(o.y);
    o.z = (o.z > 0.f) ? o.z : expm1f(o.z);
    o.w = (o.w > 0.f) ? o.w : expm1f(o.w);
    ((float4*)g_hg)[(size_t)gw * (IN_DIM / 4) + lane] = o;
}

// ---------------- node: proj + gate + blend (fused-weight form) ----------
__global__ void __launch_bounds__(NTHR, 1) k_node_tc(
    const float* __restrict__ ctx, const float* __restrict__ bp,
    float* __restrict__ out) {
    extern __shared__ __align__(16) unsigned short sm[];
    unsigned short* Ahi = sm;
    unsigned short* Alo = sm + TILE_U16;
    unsigned short* Bt  = sm + 2 * TILE_U16;
    unsigned short* Chi = sm + 4 * TILE_U16;
    unsigned short* Clo = sm + 5 * TILE_U16;
    int tid = threadIdx.x, wid = tid >> 5, lane = tid & 31;
    int g = lane >> 2, t = lane & 3;
    long nodebase = (long)blockIdx.x * MTILE;
    int m0 = (wid >> 2) * 32, n0 = (wid & 3) * 32;

    fill_A(Ahi, Alo, g_hg, nodebase, tid);
    fill_A(Chi, Clo, ctx, nodebase, tid);
    copy_B(Bt, g_WpT, tid);
    __syncthreads();

    // GEMM1: hp(no bias) = hg @ Wp^T
    float pacc[2][4][4];
#pragma unroll
    for (int a = 0; a < 2; a++)
#pragma unroll
        for (int b = 0; b < 4; b++)
#pragma unroll
            for (int c = 0; c < 4; c++) pacc[a][b][c] = 0.f;
    gemm_tile<4>(pacc, (const uint32_t*)Ahi, (const uint32_t*)Alo,
                 (const uint32_t*)Bt, (const uint32_t*)(Bt + TILE_U16), m0, n0, g, t);
    __syncthreads();

    // GEMM2: gate = hg @ Wpg^T (same A tiles)
    copy_B(Bt, g_WpgT, tid);
    __syncthreads();
    float gacc[2][4][4];
#pragma unroll
    for (int a = 0; a < 2; a++)
#pragma unroll
        for (int b = 0; b < 4; b++)
#pragma unroll
            for (int c = 0; c < 4; c++) gacc[a][b][c] = 0.f;
    gemm_tile<4>(gacc, (const uint32_t*)Ahi, (const uint32_t*)Alo,
                 (const uint32_t*)Bt, (const uint32_t*)(Bt + TILE_U16), m0, n0, g, t);
    __syncthreads();

    // GEMM3: gate += ctx @ Wg2^T
    copy_B(Bt, g_WgT + 2 * TILE_U16, tid);
    __syncthreads();
    gemm_tile<4>(gacc, (const uint32_t*)Chi, (const uint32_t*)Clo,
                 (const uint32_t*)Bt, (const uint32_t*)(Bt + TILE_U16), m0, n0, g, t);

    // epilogue
#pragma unroll
    for (int nt = 0; nt < 4; nt++) {
        int col = n0 + nt * 8 + 2 * t;
        float2 bpv = *(const float2*)&bp[col];
        float2 bfv = *(const float2*)&g_bfuse[col];
#pragma unroll
        for (int mt = 0; mt < 2; mt++) {
            int lr0 = m0 + mt * 16 + g, lr1 = lr0 + 8;
            long r0 = nodebase + lr0, r1 = nodebase + lr1;
            if (r0 < NN) {
                float2 cv = recon2(Chi, Clo, lr0 * TS + col);
                float h0 = pacc[mt][nt][0] + bpv.x, h1 = pacc[mt][nt][1] + bpv.y;
                float s0 = 1.f / (1.f + __expf(-(gacc[mt][nt][0] + bfv.x)));
                float s1 = 1.f / (1.f + __expf(-(gacc[mt][nt][1] + bfv.y)));
                *(float2*)&out[r0 * IN_DIM + col] =
                    make_float2(s0 * h0 + (1.f - s0) * cv.x, s1 * h1 + (1.f - s1) * cv.y);
            }
            if (r1 < NN) {
                float2 cv = recon2(Chi, Clo, lr1 * TS + col);
                float h2 = pacc[mt][nt][2] + bpv.x, h3 = pacc[mt][nt][3] + bpv.y;
                float s2 = 1.f / (1.f + __expf(-(gacc[mt][nt][2] + bfv.x)));
                float s3 = 1.f / (1.f + __expf(-(gacc[mt][nt][3] + bfv.y)));
                *(float2*)&out[r1 * IN_DIM + col] =
                    make_float2(s2 * h2 + (1.f - s2) * cv.x, s3 * h3 + (1.f - s3) * cv.y);
            }
        }
    }
}

// ---------------- launch ----------------
#define SMEM_FEAT (4 * TILE_B)     // 139264
#define SMEM_NODE (6 * TILE_B)     // 208896

extern "C" void kernel_launch(void* const* d_in, const int* in_sizes, int n_in,
                              void* d_out, int out_size) {
    const float* h    = (const float*)d_in[0];
    const int*   src  = (const int*)d_in[1];
    const int*   dst  = (const int*)d_in[2];
    const float* ctx  = (const float*)d_in[3];
    const float* Wfc  = (const float*)d_in[4];
    const float* al   = (const float*)d_in[5];
    const float* ar   = (const float*)d_in[6];
    const float* bgat = (const float*)d_in[7];
    const float* Wp   = (const float*)d_in[8];
    const float* bp   = (const float*)d_in[9];
    const float* Wg   = (const float*)d_in[10];
    const float* bg   = (const float*)d_in[11];
    float* out = (float*)d_out;

    static int inited = 0;
    static cudaStream_t s1, s2;
    static cudaEvent_t evA, evB, evD;
    if (!inited) {
        cudaFuncSetAttribute(k_feat_tc, cudaFuncAttributeMaxDynamicSharedMemorySize, SMEM_FEAT);
        cudaFuncSetAttribute(k_node_tc, cudaFuncAttributeMaxDynamicSharedMemorySize, SMEM_NODE);
        cudaStreamCreateWithFlags(&s1, cudaStreamNonBlocking);
        cudaStreamCreateWithFlags(&s2, cudaStreamNonBlocking);
        cudaEventCreateWithFlags(&evA, cudaEventDisableTiming);
        cudaEventCreateWithFlags(&evB, cudaEventDisableTiming);
        cudaEventCreateWithFlags(&evD, cudaEventDisableTiming);
        inited = 1;
    }

    // fork
    cudaEventRecord(evA, 0);
    cudaStreamWaitEvent(s1, evA, 0);
    cudaStreamWaitEvent(s2, evA, 0);

    // s1: weight prep for node's Wp/Wg2, then CSR build (R11's proven order)
    k_prepw_pg<<<192, 256, 0, s1>>>(Wp, Wg);
    k_init<<<(NN + 255) / 256, 256, 0, s1>>>();
    k_hist<<<(EE + 255) / 256, 256, 0, s1>>>(dst);
    k_scan1<<<NBLK_SCAN, 256, 0, s1>>>();
    k_scan2<<<1, 256, 0, s1>>>();
    k_scatter<<<(EE + 255) / 256, 256, 0, s1>>>(src, dst);
    cudaEventRecord(evB, s1);

    // s2: Wpg product + fused bias (tiny, runs before feat fills the chip)
    k_prepmm<<<64, 256, 0, s2>>>(Wp, Wg, bp, bg);
    cudaEventRecord(evD, s2);

    // main: Wfc prep, feat
    k_prepw_fc<<<64, 256>>>(Wfc);
    k_feat_tc<<<NCTA_GEMM, NTHR, SMEM_FEAT>>>(h, al, ar);

    // join, aggregate, node
    cudaStreamWaitEvent(0, evB, 0);
    k_agg<<<(NN * 32 + 255) / 256, 256>>>(bgat);
    cudaStreamWaitEvent(0, evD, 0);
    k_node_tc<<<NCTA_GEMM, NTHR, SMEM_NODE>>>(ctx, bp, out);
}

// round 15
// speedup vs baseline: 1.3196x; 1.0490x over previous
#include <cuda_runtime.h>
#include <cuda_bf16.h>
#include <math.h>
#include <stdint.h>

#define NN 50000
#define EE 800000
#define IN_DIM 128
#define HH 4
#define NEG_SLOPE 0.2f
#define NBLK_SCAN 196
#define MTILE 128
#define NCTA_GEMM 391
#define TS 136
#define TILE_U16 (128 * TS)
#define TILE_B (TILE_U16 * 2)
#define NTHR 512

// ---------------- scratch ----------------
__device__ float g_feat[(size_t)NN * IN_DIM];
__device__ float g_el[NN * HH];
__device__ float g_er[NN * HH];
__device__ float g_hg[(size_t)NN * IN_DIM];
__device__ int   g_cnt[NN];
__device__ int   g_off[NN];
__device__ int   g_cur[NN];
__device__ int   g_esrc[EE];
__device__ int   g_bsum[256];
__device__ __align__(16) unsigned short g_WfcT[2 * TILE_U16];
__device__ __align__(16) unsigned short g_WpT[2 * TILE_U16];
__device__ __align__(16) unsigned short g_WgT[4 * TILE_U16];

// ---------------- helpers ----------------
__device__ __forceinline__ unsigned short bfb(__nv_bfloat16 v) {
    return *reinterpret_cast<unsigned short*>(&v);
}
__device__ __forceinline__ void split2(float x0, float x1, uint32_t& hi, uint32_t& lo) {
    __nv_bfloat16 h0 = __float2bfloat16(x0), h1 = __float2bfloat16(x1);
    __nv_bfloat16 l0 = __float2bfloat16(x0 - __bfloat162float(h0));
    __nv_bfloat16 l1 = __float2bfloat16(x1 - __bfloat162float(h1));
    hi = (uint32_t)bfb(h0) | ((uint32_t)bfb(h1) << 16);
    lo = (uint32_t)bfb(l0) | ((uint32_t)bfb(l1) << 16);
}
__device__ __forceinline__ float2 recon2(const unsigned short* Hi, const unsigned short* Lo, int idx) {
    __nv_bfloat162 h = *(const __nv_bfloat162*)&Hi[idx];
    __nv_bfloat162 l = *(const __nv_bfloat162*)&Lo[idx];
    float2 hf = __bfloat1622float2(h);
    float2 lf = __bfloat1622float2(l);
    return make_float2(hf.x + lf.x, hf.y + lf.y);
}
__device__ __forceinline__ void hmma(float* c, uint32_t a0, uint32_t a1, uint32_t a2, uint32_t a3,
                                     uint32_t b0, uint32_t b1) {
    asm volatile(
        "mma.sync.aligned.m16n8k16.row.col.f32.bf16.bf16.f32 "
        "{%0,%1,%2,%3}, {%4,%5,%6,%7}, {%8,%9}, {%0,%1,%2,%3};"
        : "+f"(c[0]), "+f"(c[1]), "+f"(c[2]), "+f"(c[3])
        : "r"(a0), "r"(a1), "r"(a2), "r"(a3), "r"(b0), "r"(b1));
}

template <int NT>
__device__ __forceinline__ void gemm_tile(float acc[2][NT][4],
    const uint32_t* Ahi, const uint32_t* Alo,
    const uint32_t* Bhi, const uint32_t* Blo,
    int m0, int n0, int g, int t) {
#pragma unroll
    for (int ks = 0; ks < 8; ks++) {
        int k0 = ks * 16;
        uint32_t ah[2][4], al[2][4];
#pragma unroll
        for (int mt = 0; mt < 2; mt++) {
            int r = m0 + mt * 16 + g;
            int i0 = (r * TS + k0 + 2 * t) >> 1;
            int i1 = ((r + 8) * TS + k0 + 2 * t) >> 1;
            ah[mt][0] = Ahi[i0]; ah[mt][1] = Ahi[i1];
            ah[mt][2] = Ahi[i0 + 4]; ah[mt][3] = Ahi[i1 + 4];
            al[mt][0] = Alo[i0]; al[mt][1] = Alo[i1];
            al[mt][2] = Alo[i0 + 4]; al[mt][3] = Alo[i1 + 4];
        }
#pragma unroll
        for (int nt = 0; nt < NT; nt++) {
            int c = n0 + nt * 8 + g;
            int bi = (c * TS + k0 + 2 * t) >> 1;
            uint32_t bh0 = Bhi[bi], bh1 = Bhi[bi + 4];
            uint32_t bl0 = Blo[bi], bl1 = Blo[bi + 4];
#pragma unroll
            for (int mt = 0; mt < 2; mt++) {
                hmma(acc[mt][nt], ah[mt][0], ah[mt][1], ah[mt][2], ah[mt][3], bh0, bh1);
                hmma(acc[mt][nt], ah[mt][0], ah[mt][1], ah[mt][2], ah[mt][3], bl0, bl1);
                hmma(acc[mt][nt], al[mt][0], al[mt][1], al[mt][2], al[mt][3], bh0, bh1);
            }
        }
    }
}

__device__ __forceinline__ void fill_A(unsigned short* Ahi, unsigned short* Alo,
                                       const float* __restrict__ src, long nodebase,
                                       int tid) {
    int m = tid >> 2, q = tid & 3;
    long node = nodebase + m;
    const float* row = src + node * IN_DIM + q * 32;
    uint32_t* H = (uint32_t*)Ahi;
    uint32_t* L = (uint32_t*)Alo;
#pragma unroll
    for (int k4 = 0; k4 < 32; k4 += 4) {
        float4 v = make_float4(0.f, 0.f, 0.f, 0.f);
        if (node < NN) v = *(const float4*)(row + k4);
        uint32_t h01, l01, h23, l23;
        split2(v.x, v.y, h01, l01);
        split2(v.z, v.w, h23, l23);
        int idx = (m * TS + q * 32 + k4) >> 1;
        H[idx] = h01; H[idx + 1] = h23;
        L[idx] = l01; L[idx + 1] = l23;
    }
}

__device__ __forceinline__ void copy_B(unsigned short* dst, const unsigned short* src, int tid) {
    const uint4* s = (const uint4*)src;
    uint4* d = (uint4*)dst;
#pragma unroll
    for (int i = tid; i < 2 * TILE_B / 16; i += NTHR) d[i] = s[i];
}

// ---------------- small kernels ----------------
__global__ void k_init() {
    int i = blockIdx.x * blockDim.x + threadIdx.x;
    if (i < NN) { g_cnt[i] = 0; g_cur[i] = 0; }
}

__global__ void k_hist(const int* __restrict__ dst) {
    int e = blockIdx.x * blockDim.x + threadIdx.x;
    if (e < EE) atomicAdd(&g_cnt[dst[e]], 1);
}

// Wfc prep only (critical path for feat)
__global__ void k_prepw_fc(const float* __restrict__ Wfc) {
    int id = blockIdx.x * 256 + threadIdx.x;
    if (id >= 16384) return;
    int n = id >> 7, k = id & 127;
    float w = Wfc[k * 128 + n];
    __nv_bfloat16 hi = __float2bfloat16(w);
    __nv_bfloat16 lo = __float2bfloat16(w - __bfloat162float(hi));
    g_WfcT[n * TS + k] = bfb(hi);
    g_WfcT[TILE_U16 + n * TS + k] = bfb(lo);
}

// Wp + Wg prep (side stream, needed only by k_node)
__global__ void k_prepw_pg(const float* __restrict__ Wp, const float* __restrict__ Wg) {
    int id = blockIdx.x * 256 + threadIdx.x;   // 49152
    if (id < 16384) {
        int n = id >> 7, k = id & 127;
        float w = Wp[k * 128 + n];
        __nv_bfloat16 hi = __float2bfloat16(w);
        __nv_bfloat16 lo = __float2bfloat16(w - __bfloat162float(hi));
        g_WpT[n * TS + k] = bfb(hi);
        g_WpT[TILE_U16 + n * TS + k] = bfb(lo);
    } else if (id < 49152) {
        int e = id - 16384;
        int n = e & 127, k = e >> 7;
        float w = Wg[k * 128 + n];
        int stage = k >> 7, kk = k & 127;
        __nv_bfloat16 hi = __float2bfloat16(w);
        __nv_bfloat16 lo = __float2bfloat16(w - __bfloat162float(hi));
        g_WgT[stage * 2 * TILE_U16 + n * TS + kk] = bfb(hi);
        g_WgT[stage * 2 * TILE_U16 + TILE_U16 + n * TS + kk] = bfb(lo);
    }
}

// ---------------- feat = h @ W_fc, fused el/er ----------------
__global__ void __launch_bounds__(NTHR, 1) k_feat_tc(const float* __restrict__ h,
                                                     const float* __restrict__ al,
                                                     const float* __restrict__ ar) {
    extern __shared__ __align__(16) unsigned short sm[];
    unsigned short* Ahi = sm;
    unsigned short* Alo = sm + TILE_U16;
    unsigned short* Bt  = sm + 2 * TILE_U16;
    int tid = threadIdx.x, wid = tid >> 5, lane = tid & 31;
    int g = lane >> 2, t = lane & 3;
    long nodebase = (long)blockIdx.x * MTILE;

    fill_A(Ahi, Alo, h, nodebase, tid);
    copy_B(Bt, g_WfcT, tid);
    __syncthreads();

    float acc[2][4][4];
#pragma unroll
    for (int a = 0; a < 2; a++)
#pragma unroll
        for (int b = 0; b < 4; b++)
#pragma unroll
            for (int c = 0; c < 4; c++) acc[a][b][c] = 0.f;

    int m0 = (wid >> 2) * 32, n0 = (wid & 3) * 32;
    gemm_tile<4>(acc, (const uint32_t*)Ahi, (const uint32_t*)Alo,
                 (const uint32_t*)Bt, (const uint32_t*)(Bt + TILE_U16), m0, n0, g, t);

    int head = wid & 3;
    float pl[4] = {0.f, 0.f, 0.f, 0.f};
    float pr[4] = {0.f, 0.f, 0.f, 0.f};
#pragma unroll
    for (int nt = 0; nt < 4; nt++) {
        int col = n0 + nt * 8 + 2 * t;
        float a0 = __ldg(&al[col]), a1 = __ldg(&al[col + 1]);
        float b0 = __ldg(&ar[col]), b1 = __ldg(&ar[col + 1]);
#pragma unroll
        for (int mt = 0; mt < 2; mt++) {
            pl[2 * mt]     += acc[mt][nt][0] * a0 + acc[mt][nt][1] * a1;
            pl[2 * mt + 1] += acc[mt][nt][2] * a0 + acc[mt][nt][3] * a1;
            pr[2 * mt]     += acc[mt][nt][0] * b0 + acc[mt][nt][1] * b1;
            pr[2 * mt + 1] += acc[mt][nt][2] * b0 + acc[mt][nt][3] * b1;
        }
    }
#pragma unroll
    for (int off = 1; off <= 2; off <<= 1) {
#pragma unroll
        for (int i = 0; i < 4; i++) {
            pl[i] += __shfl_xor_sync(0xffffffffu, pl[i], off);
            pr[i] += __shfl_xor_sync(0xffffffffu, pr[i], off);
        }
    }
    if (t == 0) {
#pragma unroll
        for (int mt = 0; mt < 2; mt++) {
            long r0 = nodebase + m0 + mt * 16 + g;
            long r1 = r0 + 8;
            if (r0 < NN) { g_el[r0 * HH + head] = pl[2 * mt];     g_er[r0 * HH + head] = pr[2 * mt]; }
            if (r1 < NN) { g_el[r1 * HH + head] = pl[2 * mt + 1]; g_er[r1 * HH + head] = pr[2 * mt + 1]; }
        }
    }

#pragma unroll
    for (int mt = 0; mt < 2; mt++) {
        long r0 = nodebase + m0 + mt * 16 + g;
        long r1 = r0 + 8;
#pragma unroll
        for (int nt = 0; nt < 4; nt++) {
            int col = n0 + nt * 8 + 2 * t;
            if (r0 < NN) *(float2*)&g_feat[r0 * IN_DIM + col] = make_float2(acc[mt][nt][0], acc[mt][nt][1]);
            if (r1 < NN) *(float2*)&g_feat[r1 * IN_DIM + col] = make_float2(acc[mt][nt][2], acc[mt][nt][3]);
        }
    }
}

// ---------------- scans / scatter ----------------
__global__ void k_scan1() {
    __shared__ int s[256];
    int i = blockIdx.x * 256 + threadIdx.x;
    int v = (i < NN) ? g_cnt[i] : 0;
    s[threadIdx.x] = v;
    __syncthreads();
#pragma unroll
    for (int off = 1; off < 256; off <<= 1) {
        int tv = (threadIdx.x >= off) ? s[threadIdx.x - off] : 0;
        __syncthreads();
        s[threadIdx.x] += tv;
        __syncthreads();
    }
    if (i < NN) g_off[i] = s[threadIdx.x] - v;
    if (threadIdx.x == 255) g_bsum[blockIdx.x] = s[255];
}

__global__ void k_scan2() {
    __shared__ int s[256];
    int t = threadIdx.x;
    int v = (t < NBLK_SCAN) ? g_bsum[t] : 0;
    s[t] = v;
    __syncthreads();
#pragma unroll
    for (int off = 1; off < 256; off <<= 1) {
        int tv = (t >= off) ? s[t - off] : 0;
        __syncthreads();
        s[t] += tv;
        __syncthreads();
    }
    if (t < NBLK_SCAN) g_bsum[t] = s[t] - v;
}

__global__ void k_scatter(const int* __restrict__ src, const int* __restrict__ dst) {
    int e = blockIdx.x * blockDim.x + threadIdx.x;
    if (e >= EE) return;
    int d = dst[e];
    int pos = atomicAdd(&g_cur[d], 1);
    g_esrc[g_off[d] + g_bsum[d >> 8] + pos] = src[e];
}

// ---------------- aggregate: warp per node, 4 edges/iter ----------------
__global__ void k_agg(const float* __restrict__ bgat) {
    int gw = (blockIdx.x * blockDim.x + threadIdx.x) >> 5;
    if (gw >= NN) return;
    int lane = threadIdx.x & 31;
    int beg = g_off[gw] + g_bsum[gw >> 8];
    int end = beg + g_cnt[gw];
    float er_h = (lane < HH) ? g_er[gw * HH + lane] : 0.f;
    float er16 = __shfl_sync(0xffffffffu, er_h, lane & 3);
    int hd = lane >> 3;
    float4 acc = make_float4(0.f, 0.f, 0.f, 0.f);
    float dsum = 0.f;
    int i = beg;
    for (; i + 3 < end; i += 4) {
        int s0 = __ldcs(&g_esrc[i]);
        int s1 = __ldcs(&g_esrc[i + 1]);
        int s2 = __ldcs(&g_esrc[i + 2]);
        int s3 = __ldcs(&g_esrc[i + 3]);
        float a = 0.f;
        if (lane < 16) {
            int eix = lane >> 2;
            int sx = (eix == 0) ? s0 : (eix == 1) ? s1 : (eix == 2) ? s2 : s3;
            float e = g_el[sx * HH + (lane & 3)] + er16;
            e = (e > 0.f) ? e : NEG_SLOPE * e;
            a = __expf(e);
        }
        float a0 = __shfl_sync(0xffffffffu, a, hd);
        float a1 = __shfl_sync(0xffffffffu, a, 4 + hd);
        float a2 = __shfl_sync(0xffffffffu, a, 8 + hd);
        float a3 = __shfl_sync(0xffffffffu, a, 12 + hd);
        dsum += (a0 + a1) + (a2 + a3);
        float4 f0 = ((const float4*)g_feat)[(size_t)s0 * (IN_DIM / 4) + lane];
        float4 f1 = ((const float4*)g_feat)[(size_t)s1 * (IN_DIM / 4) + lane];
        float4 f2 = ((const float4*)g_feat)[(size_t)s2 * (IN_DIM / 4) + lane];
        float4 f3 = ((const float4*)g_feat)[(size_t)s3 * (IN_DIM / 4) + lane];
        acc.x = fmaf(f0.x, a0, acc.x); acc.y = fmaf(f0.y, a0, acc.y);
        acc.z = fmaf(f0.z, a0, acc.z); acc.w = fmaf(f0.w, a0, acc.w);
        acc.x = fmaf(f1.x, a1, acc.x); acc.y = fmaf(f1.y, a1, acc.y);
        acc.z = fmaf(f1.z, a1, acc.z); acc.w = fmaf(f1.w, a1, acc.w);
        acc.x = fmaf(f2.x, a2, acc.x); acc.y = fmaf(f2.y, a2, acc.y);
        acc.z = fmaf(f2.z, a2, acc.z); acc.w = fmaf(f2.w, a2, acc.w);
        acc.x = fmaf(f3.x, a3, acc.x); acc.y = fmaf(f3.y, a3, acc.y);
        acc.z = fmaf(f3.z, a3, acc.z); acc.w = fmaf(f3.w, a3, acc.w);
    }
    for (; i < end; i++) {
        int s0 = __ldcs(&g_esrc[i]);
        float a = 0.f;
        if (lane < 4) {
            float e = g_el[s0 * HH + lane] + er16;
            e = (e > 0.f) ? e : NEG_SLOPE * e;
            a = __expf(e);
        }
        float a0 = __shfl_sync(0xffffffffu, a, hd);
        dsum += a0;
        float4 f0 = ((const float4*)g_feat)[(size_t)s0 * (IN_DIM / 4) + lane];
        acc.x = fmaf(f0.x, a0, acc.x); acc.y = fmaf(f0.y, a0, acc.y);
        acc.z = fmaf(f0.z, a0, acc.z); acc.w = fmaf(f0.w, a0, acc.w);
    }
    float inv = (dsum > 0.f) ? (1.f / dsum) : 0.f;
    float4 b = ((const float4*)bgat)[lane];
    float4 o;
    o.x = acc.x * inv + b.x; o.y = acc.y * inv + b.y;
    o.z = acc.z * inv + b.z; o.w = acc.w * inv + b.w;
    o.x = (o.x > 0.f) ? o.x : expm1f(o.x);
    o.y = (o.y > 0.f) ? o.y : expm1f(o.y);
    o.z = (o.z > 0.f) ? o.z : expm1f(o.z);
    o.w = (o.w > 0.f) ? o.w : expm1f(o.w);
    ((float4*)g_hg)[(size_t)gw * (IN_DIM / 4) + lane] = o;
}

// ---------------- node: proj + gate + blend, 3-region smem ----------------
__global__ void __launch_bounds__(NTHR, 1) k_node_tc(
    const float* __restrict__ ctx, const float* __restrict__ bp,
    const float* __restrict__ bg, float* __restrict__ out) {
    extern __shared__ __align__(16) unsigned short sm[];
    unsigned short* Ahi = sm;                      // hg, then hp (split)
    unsigned short* Alo = sm + TILE_U16;
    unsigned short* Bt  = sm + 2 * TILE_U16;       // Wp -> Wg1 -> Wg2
    unsigned short* Chi = sm + 4 * TILE_U16;       // ctx (split), persistent
    unsigned short* Clo = sm + 5 * TILE_U16;
    int tid = threadIdx.x, wid = tid >> 5, lane = tid & 31;
    int g = lane >> 2, t = lane & 3;
    long nodebase = (long)blockIdx.x * MTILE;
    int m0 = (wid >> 2) * 32, n0 = (wid & 3) * 32;

    fill_A(Ahi, Alo, g_hg, nodebase, tid);
    fill_A(Chi, Clo, ctx, nodebase, tid);
    copy_B(Bt, g_WpT, tid);
    __syncthreads();

    // phase 1: hp = hg @ Wp^T
    float acc[2][4][4];
#pragma unroll
    for (int a = 0; a < 2; a++)
#pragma unroll
        for (int b = 0; b < 4; b++)
#pragma unroll
            for (int c = 0; c < 4; c++) acc[a][b][c] = 0.f;

    gemm_tile<4>(acc, (const uint32_t*)Ahi, (const uint32_t*)Alo,
                 (const uint32_t*)Bt, (const uint32_t*)(Bt + TILE_U16), m0, n0, g, t);
    __syncthreads();

    // hp = acc + bias -> re-split into A tiles (epilogue hp source too)
    {
        uint32_t* H = (uint32_t*)Ahi;
        uint32_t* L = (uint32_t*)Alo;
#pragma unroll
        for (int nt = 0; nt < 4; nt++) {
            int col = n0 + nt * 8 + 2 * t;
            float2 bpv = *(const float2*)&bp[col];
#pragma unroll
            for (int mt = 0; mt < 2; mt++) {
                int r0 = m0 + mt * 16 + g, r1 = r0 + 8;
                float h0 = acc[mt][nt][0] + bpv.x, h1 = acc[mt][nt][1] + bpv.y;
                float h2 = acc[mt][nt][2] + bpv.x, h3 = acc[mt][nt][3] + bpv.y;
                uint32_t hi, lo;
                split2(h0, h1, hi, lo);
                H[(r0 * TS + col) >> 1] = hi;
                L[(r0 * TS + col) >> 1] = lo;
                split2(h2, h3, hi, lo);
                H[(r1 * TS + col) >> 1] = hi;
                L[(r1 * TS + col) >> 1] = lo;
            }
        }
    }
    copy_B(Bt, g_WgT, tid);
    __syncthreads();

    // phase 2: gate = hp @ Wg1^T
#pragma unroll
    for (int a = 0; a < 2; a++)
#pragma unroll
        for (int b = 0; b < 4; b++)
#pragma unroll
            for (int c = 0; c < 4; c++) acc[a][b][c] = 0.f;
    gemm_tile<4>(acc, (const uint32_t*)Ahi, (const uint32_t*)Alo,
                 (const uint32_t*)Bt, (const uint32_t*)(Bt + TILE_U16), m0, n0, g, t);
    __syncthreads();

    // phase 3: gate += ctx @ Wg2^T  (ctx tiles resident in region C)
    copy_B(Bt, g_WgT + 2 * TILE_U16, tid);
    __syncthreads();
    gemm_tile<4>(acc, (const uint32_t*)Chi, (const uint32_t*)Clo,
                 (const uint32_t*)Bt, (const uint32_t*)(Bt + TILE_U16), m0, n0, g, t);

    // epilogue: hp/ctx reconstructed from smem tiles (hi+lo), sigmoid, blend
#pragma unroll
    for (int nt = 0; nt < 4; nt++) {
        int col = n0 + nt * 8 + 2 * t;
        float2 bgv = *(const float2*)&bg[col];
#pragma unroll
        for (int mt = 0; mt < 2; mt++) {
            int lr0 = m0 + mt * 16 + g, lr1 = lr0 + 8;
            long r0 = nodebase + lr0, r1 = nodebase + lr1;
            if (r0 < NN) {
                float2 cv = recon2(Chi, Clo, lr0 * TS + col);
                float2 hv = recon2(Ahi, Alo, lr0 * TS + col);
                float s0 = 1.f / (1.f + __expf(-(acc[mt][nt][0] + bgv.x)));
                float s1 = 1.f / (1.f + __expf(-(acc[mt][nt][1] + bgv.y)));
                *(float2*)&out[r0 * IN_DIM + col] =
                    make_float2(s0 * hv.x + (1.f - s0) * cv.x, s1 * hv.y + (1.f - s1) * cv.y);
            }
            if (r1 < NN) {
                float2 cv = recon2(Chi, Clo, lr1 * TS + col);
                float2 hv = recon2(Ahi, Alo, lr1 * TS + col);
                float s2 = 1.f / (1.f + __expf(-(acc[mt][nt][2] + bgv.x)));
                float s3 = 1.f / (1.f + __expf(-(acc[mt][nt][3] + bgv.y)));
                *(float2*)&out[r1 * IN_DIM + col] =
                    make_float2(s2 * hv.x + (1.f - s2) * cv.x, s3 * hv.y + (1.f - s3) * cv.y);
            }
        }
    }
}

// ---------------- launch ----------------
#define SMEM_FEAT (4 * TILE_B)     // 139264
#define SMEM_NODE (6 * TILE_B)     // 208896

extern "C" void kernel_launch(void* const* d_in, const int* in_sizes, int n_in,
                              void* d_out, int out_size) {
    const float* h    = (const float*)d_in[0];
    const int*   src  = (const int*)d_in[1];
    const int*   dst  = (const int*)d_in[2];
    const float* ctx  = (const float*)d_in[3];
    const float* Wfc  = (const float*)d_in[4];
    const float* al   = (const float*)d_in[5];
    const float* ar   = (const float*)d_in[6];
    const float* bgat = (const float*)d_in[7];
    const float* Wp   = (const float*)d_in[8];
    const float* bp   = (const float*)d_in[9];
    const float* Wg   = (const float*)d_in[10];
    const float* bg   = (const float*)d_in[11];
    float* out = (float*)d_out;

    static int inited = 0;
    static cudaStream_t s1;
    static cudaEvent_t evA, evB;
    if (!inited) {
        cudaFuncSetAttribute(k_feat_tc, cudaFuncAttributeMaxDynamicSharedMemorySize, SMEM_FEAT);
        cudaFuncSetAttribute(k_node_tc, cudaFuncAttributeMaxDynamicSharedMemorySize, SMEM_NODE);
        cudaStreamCreateWithFlags(&s1, cudaStreamNonBlocking);
        cudaEventCreateWithFlags(&evA, cudaEventDisableTiming);
        cudaEventCreateWithFlags(&evB, cudaEventDisableTiming);
        inited = 1;
    }

    // fork: side stream does Wp/Wg prep + CSR build (R11's proven order)
    cudaEventRecord(evA, 0);
    cudaStreamWaitEvent(s1, evA, 0);
    k_prepw_pg<<<192, 256, 0, s1>>>(Wp, Wg);
    k_init<<<(NN + 255) / 256, 256, 0, s1>>>();
    k_hist<<<(EE + 255) / 256, 256, 0, s1>>>(dst);
    k_scan1<<<NBLK_SCAN, 256, 0, s1>>>();
    k_scan2<<<1, 256, 0, s1>>>();
    k_scatter<<<(EE + 255) / 256, 256, 0, s1>>>(src, dst);
    cudaEventRecord(evB, s1);

    // main: Wfc prep, feat
    k_prepw_fc<<<64, 256>>>(Wfc);
    k_feat_tc<<<NCTA_GEMM, NTHR, SMEM_FEAT>>>(h, al, ar);

    // join, aggregate, node
    cudaStreamWaitEvent(0, evB, 0);
    k_agg<<<(NN * 32 + 255) / 256, 256>>>(bgat);
    k_node_tc<<<NCTA_GEMM, NTHR, SMEM_NODE>>>(ctx, bp, bg, out);
}

// round 16
// speedup vs baseline: 1.3232x; 1.0027x over previous
#include <cuda_runtime.h>
#include <cuda_bf16.h>
#include <math.h>
#include <stdint.h>

#define NN 50000
#define EE 800000
#define IN_DIM 128
#define HH 4
#define NEG_SLOPE 0.2f
#define NBLK_SCAN 196
#define MTILE 128
#define NCTA_GEMM 391
#define TS 136
#define TILE_U16 (128 * TS)
#define TILE_B (TILE_U16 * 2)
#define NTHR 512

// ---------------- scratch ----------------
__device__ float g_feat[(size_t)NN * IN_DIM];
__device__ float g_el[NN * HH];
__device__ float g_er[NN * HH];
__device__ float g_hg[(size_t)NN * IN_DIM];
__device__ int   g_cnt[NN];
__device__ int   g_off[NN];
__device__ int   g_cur[NN];
__device__ int   g_esrc[EE];
__device__ int   g_bsum[256];
__device__ __align__(16) unsigned short g_WfcT[2 * TILE_U16];
__device__ __align__(16) unsigned short g_WpT[2 * TILE_U16];
__device__ __align__(16) unsigned short g_WgT[4 * TILE_U16];

// ---------------- helpers ----------------
__device__ __forceinline__ unsigned short bfb(__nv_bfloat16 v) {
    return *reinterpret_cast<unsigned short*>(&v);
}
__device__ __forceinline__ void split2(float x0, float x1, uint32_t& hi, uint32_t& lo) {
    __nv_bfloat16 h0 = __float2bfloat16(x0), h1 = __float2bfloat16(x1);
    __nv_bfloat16 l0 = __float2bfloat16(x0 - __bfloat162float(h0));
    __nv_bfloat16 l1 = __float2bfloat16(x1 - __bfloat162float(h1));
    hi = (uint32_t)bfb(h0) | ((uint32_t)bfb(h1) << 16);
    lo = (uint32_t)bfb(l0) | ((uint32_t)bfb(l1) << 16);
}
__device__ __forceinline__ float2 recon2(const unsigned short* Hi, const unsigned short* Lo, int idx) {
    __nv_bfloat162 h = *(const __nv_bfloat162*)&Hi[idx];
    __nv_bfloat162 l = *(const __nv_bfloat162*)&Lo[idx];
    float2 hf = __bfloat1622float2(h);
    float2 lf = __bfloat1622float2(l);
    return make_float2(hf.x + lf.x, hf.y + lf.y);
}
__device__ __forceinline__ void hmma(float* c, uint32_t a0, uint32_t a1, uint32_t a2, uint32_t a3,
                                     uint32_t b0, uint32_t b1) {
    asm volatile(
        "mma.sync.aligned.m16n8k16.row.col.f32.bf16.bf16.f32 "
        "{%0,%1,%2,%3}, {%4,%5,%6,%7}, {%8,%9}, {%0,%1,%2,%3};"
        : "+f"(c[0]), "+f"(c[1]), "+f"(c[2]), "+f"(c[3])
        : "r"(a0), "r"(a1), "r"(a2), "r"(a3), "r"(b0), "r"(b1));
}

template <int NT>
__device__ __forceinline__ void gemm_tile(float acc[2][NT][4],
    const uint32_t* Ahi, const uint32_t* Alo,
    const uint32_t* Bhi, const uint32_t* Blo,
    int m0, int n0, int g, int t) {
#pragma unroll
    for (int ks = 0; ks < 8; ks++) {
        int k0 = ks * 16;
        uint32_t ah[2][4], al[2][4];
#pragma unroll
        for (int mt = 0; mt < 2; mt++) {
            int r = m0 + mt * 16 + g;
            int i0 = (r * TS + k0 + 2 * t) >> 1;
            int i1 = ((r + 8) * TS + k0 + 2 * t) >> 1;
            ah[mt][0] = Ahi[i0]; ah[mt][1] = Ahi[i1];
            ah[mt][2] = Ahi[i0 + 4]; ah[mt][3] = Ahi[i1 + 4];
            al[mt][0] = Alo[i0]; al[mt][1] = Alo[i1];
            al[mt][2] = Alo[i0 + 4]; al[mt][3] = Alo[i1 + 4];
        }
#pragma unroll
        for (int nt = 0; nt < NT; nt++) {
            int c = n0 + nt * 8 + g;
            int bi = (c * TS + k0 + 2 * t) >> 1;
            uint32_t bh0 = Bhi[bi], bh1 = Bhi[bi + 4];
            uint32_t bl0 = Blo[bi], bl1 = Blo[bi + 4];
#pragma unroll
            for (int mt = 0; mt < 2; mt++) {
                hmma(acc[mt][nt], ah[mt][0], ah[mt][1], ah[mt][2], ah[mt][3], bh0, bh1);
                hmma(acc[mt][nt], ah[mt][0], ah[mt][1], ah[mt][2], ah[mt][3], bl0, bl1);
                hmma(acc[mt][nt], al[mt][0], al[mt][1], al[mt][2], al[mt][3], bh0, bh1);
            }
        }
    }
}

__device__ __forceinline__ void fill_A(unsigned short* Ahi, unsigned short* Alo,
                                       const float* __restrict__ src, long nodebase,
                                       int tid) {
    int m = tid >> 2, q = tid & 3;
    long node = nodebase + m;
    const float* row = src + node * IN_DIM + q * 32;
    uint32_t* H = (uint32_t*)Ahi;
    uint32_t* L = (uint32_t*)Alo;
#pragma unroll
    for (int k4 = 0; k4 < 32; k4 += 4) {
        float4 v = make_float4(0.f, 0.f, 0.f, 0.f);
        if (node < NN) v = *(const float4*)(row + k4);
        uint32_t h01, l01, h23, l23;
        split2(v.x, v.y, h01, l01);
        split2(v.z, v.w, h23, l23);
        int idx = (m * TS + q * 32 + k4) >> 1;
        H[idx] = h01; H[idx + 1] = h23;
        L[idx] = l01; L[idx + 1] = l23;
    }
}

__device__ __forceinline__ void copy_B(unsigned short* dst, const unsigned short* src, int tid) {
    const uint4* s = (const uint4*)src;
    uint4* d = (uint4*)dst;
#pragma unroll
    for (int i = tid; i < 2 * TILE_B / 16; i += NTHR) d[i] = s[i];
}

// ---------------- small kernels ----------------
__global__ void k_init() {
    int i = blockIdx.x * blockDim.x + threadIdx.x;
    if (i < NN) { g_cnt[i] = 0; g_cur[i] = 0; }
}

__global__ void k_hist(const int* __restrict__ dst) {
    int e = blockIdx.x * blockDim.x + threadIdx.x;
    if (e < EE) atomicAdd(&g_cnt[dst[e]], 1);
}

__global__ void k_prepw_fc(const float* __restrict__ Wfc) {
    int id = blockIdx.x * 256 + threadIdx.x;
    if (id >= 16384) return;
    int n = id >> 7, k = id & 127;
    float w = Wfc[k * 128 + n];
    __nv_bfloat16 hi = __float2bfloat16(w);
    __nv_bfloat16 lo = __float2bfloat16(w - __bfloat162float(hi));
    g_WfcT[n * TS + k] = bfb(hi);
    g_WfcT[TILE_U16 + n * TS + k] = bfb(lo);
}

__global__ void k_prepw_pg(const float* __restrict__ Wp, const float* __restrict__ Wg) {
    int id = blockIdx.x * 256 + threadIdx.x;
    if (id < 16384) {
        int n = id >> 7, k = id & 127;
        float w = Wp[k * 128 + n];
        __nv_bfloat16 hi = __float2bfloat16(w);
        __nv_bfloat16 lo = __float2bfloat16(w - __bfloat162float(hi));
        g_WpT[n * TS + k] = bfb(hi);
        g_WpT[TILE_U16 + n * TS + k] = bfb(lo);
    } else if (id < 49152) {
        int e = id - 16384;
        int n = e & 127, k = e >> 7;
        float w = Wg[k * 128 + n];
        int stage = k >> 7, kk = k & 127;
        __nv_bfloat16 hi = __float2bfloat16(w);
        __nv_bfloat16 lo = __float2bfloat16(w - __bfloat162float(hi));
        g_WgT[stage * 2 * TILE_U16 + n * TS + kk] = bfb(hi);
        g_WgT[stage * 2 * TILE_U16 + TILE_U16 + n * TS + kk] = bfb(lo);
    }
}

// ---------------- feat = h @ W_fc, fused el/er; B direct from L2 --------
__global__ void __launch_bounds__(NTHR, 2) k_feat_tc(const float* __restrict__ h,
                                                     const float* __restrict__ al,
                                                     const float* __restrict__ ar) {
    extern __shared__ __align__(16) unsigned short sm[];
    unsigned short* Ahi = sm;
    unsigned short* Alo = sm + TILE_U16;
    int tid = threadIdx.x, wid = tid >> 5, lane = tid & 31;
    int g = lane >> 2, t = lane & 3;
    long nodebase = (long)blockIdx.x * MTILE;

    fill_A(Ahi, Alo, h, nodebase, tid);
    __syncthreads();

    float acc[2][4][4];
#pragma unroll
    for (int a = 0; a < 2; a++)
#pragma unroll
        for (int b = 0; b < 4; b++)
#pragma unroll
            for (int c = 0; c < 4; c++) acc[a][b][c] = 0.f;

    int m0 = (wid >> 2) * 32, n0 = (wid & 3) * 32;
    gemm_tile<4>(acc, (const uint32_t*)Ahi, (const uint32_t*)Alo,
                 (const uint32_t*)g_WfcT, (const uint32_t*)(g_WfcT + TILE_U16),
                 m0, n0, g, t);

    int head = wid & 3;
    float pl[4] = {0.f, 0.f, 0.f, 0.f};
    float pr[4] = {0.f, 0.f, 0.f, 0.f};
#pragma unroll
    for (int nt = 0; nt < 4; nt++) {
        int col = n0 + nt * 8 + 2 * t;
        float a0 = __ldg(&al[col]), a1 = __ldg(&al[col + 1]);
        float b0 = __ldg(&ar[col]), b1 = __ldg(&ar[col + 1]);
#pragma unroll
        for (int mt = 0; mt < 2; mt++) {
            pl[2 * mt]     += acc[mt][nt][0] * a0 + acc[mt][nt][1] * a1;
            pl[2 * mt + 1] += acc[mt][nt][2] * a0 + acc[mt][nt][3] * a1;
            pr[2 * mt]     += acc[mt][nt][0] * b0 + acc[mt][nt][1] * b1;
            pr[2 * mt + 1] += acc[mt][nt][2] * b0 + acc[mt][nt][3] * b1;
        }
    }
#pragma unroll
    for (int off = 1; off <= 2; off <<= 1) {
#pragma unroll
        for (int i = 0; i < 4; i++) {
            pl[i] += __shfl_xor_sync(0xffffffffu, pl[i], off);
            pr[i] += __shfl_xor_sync(0xffffffffu, pr[i], off);
        }
    }
    if (t == 0) {
#pragma unroll
        for (int mt = 0; mt < 2; mt++) {
            long r0 = nodebase + m0 + mt * 16 + g;
            long r1 = r0 + 8;
            if (r0 < NN) { g_el[r0 * HH + head] = pl[2 * mt];     g_er[r0 * HH + head] = pr[2 * mt]; }
            if (r1 < NN) { g_el[r1 * HH + head] = pl[2 * mt + 1]; g_er[r1 * HH + head] = pr[2 * mt + 1]; }
        }
    }

#pragma unroll
    for (int mt = 0; mt < 2; mt++) {
        long r0 = nodebase + m0 + mt * 16 + g;
        long r1 = r0 + 8;
#pragma unroll
        for (int nt = 0; nt < 4; nt++) {
            int col = n0 + nt * 8 + 2 * t;
            if (r0 < NN) *(float2*)&g_feat[r0 * IN_DIM + col] = make_float2(acc[mt][nt][0], acc[mt][nt][1]);
            if (r1 < NN) *(float2*)&g_feat[r1 * IN_DIM + col] = make_float2(acc[mt][nt][2], acc[mt][nt][3]);
        }
    }
}

// ---------------- scans / scatter ----------------
__global__ void k_scan1() {
    __shared__ int s[256];
    int i = blockIdx.x * 256 + threadIdx.x;
    int v = (i < NN) ? g_cnt[i] : 0;
    s[threadIdx.x] = v;
    __syncthreads();
#pragma unroll
    for (int off = 1; off < 256; off <<= 1) {
        int tv = (threadIdx.x >= off) ? s[threadIdx.x - off] : 0;
        __syncthreads();
        s[threadIdx.x] += tv;
        __syncthreads();
    }
    if (i < NN) g_off[i] = s[threadIdx.x] - v;
    if (threadIdx.x == 255) g_bsum[blockIdx.x] = s[255];
}

__global__ void k_scan2() {
    __shared__ int s[256];
    int t = threadIdx.x;
    int v = (t < NBLK_SCAN) ? g_bsum[t] : 0;
    s[t] = v;
    __syncthreads();
#pragma unroll
    for (int off = 1; off < 256; off <<= 1) {
        int tv = (t >= off) ? s[t - off] : 0;
        __syncthreads();
        s[t] += tv;
        __syncthreads();
    }
    if (t < NBLK_SCAN) g_bsum[t] = s[t] - v;
}

__global__ void k_scatter(const int* __restrict__ src, const int* __restrict__ dst) {
    int e = blockIdx.x * blockDim.x + threadIdx.x;
    if (e >= EE) return;
    int d = dst[e];
    int pos = atomicAdd(&g_cur[d], 1);
    g_esrc[g_off[d] + g_bsum[d >> 8] + pos] = src[e];
}

// ---------------- aggregate: warp per node, 4 edges/iter ----------------
__global__ void k_agg(const float* __restrict__ bgat) {
    int gw = (blockIdx.x * blockDim.x + threadIdx.x) >> 5;
    if (gw >= NN) return;
    int lane = threadIdx.x & 31;
    int beg = g_off[gw] + g_bsum[gw >> 8];
    int end = beg + g_cnt[gw];
    float er_h = (lane < HH) ? g_er[gw * HH + lane] : 0.f;
    float er16 = __shfl_sync(0xffffffffu, er_h, lane & 3);
    int hd = lane >> 3;
    float4 acc = make_float4(0.f, 0.f, 0.f, 0.f);
    float dsum = 0.f;
    int i = beg;
    for (; i + 3 < end; i += 4) {
        int s0 = __ldg(&g_esrc[i]);
        int s1 = __ldg(&g_esrc[i + 1]);
        int s2 = __ldg(&g_esrc[i + 2]);
        int s3 = __ldg(&g_esrc[i + 3]);
        float a = 0.f;
        if (lane < 16) {
            int eix = lane >> 2;
            int sx = (eix == 0) ? s0 : (eix == 1) ? s1 : (eix == 2) ? s2 : s3;
            float e = g_el[sx * HH + (lane & 3)] + er16;
            e = (e > 0.f) ? e : NEG_SLOPE * e;
            a = __expf(e);
        }
        float a0 = __shfl_sync(0xffffffffu, a, hd);
        float a1 = __shfl_sync(0xffffffffu, a, 4 + hd);
        float a2 = __shfl_sync(0xffffffffu, a, 8 + hd);
        float a3 = __shfl_sync(0xffffffffu, a, 12 + hd);
        dsum += (a0 + a1) + (a2 + a3);
        float4 f0 = ((const float4*)g_feat)[(size_t)s0 * (IN_DIM / 4) + lane];
        float4 f1 = ((const float4*)g_feat)[(size_t)s1 * (IN_DIM / 4) + lane];
        float4 f2 = ((const float4*)g_feat)[(size_t)s2 * (IN_DIM / 4) + lane];
        float4 f3 = ((const float4*)g_feat)[(size_t)s3 * (IN_DIM / 4) + lane];
        acc.x = fmaf(f0.x, a0, acc.x); acc.y = fmaf(f0.y, a0, acc.y);
        acc.z = fmaf(f0.z, a0, acc.z); acc.w = fmaf(f0.w, a0, acc.w);
        acc.x = fmaf(f1.x, a1, acc.x); acc.y = fmaf(f1.y, a1, acc.y);
        acc.z = fmaf(f1.z, a1, acc.z); acc.w = fmaf(f1.w, a1, acc.w);
        acc.x = fmaf(f2.x, a2, acc.x); acc.y = fmaf(f2.y, a2, acc.y);
        acc.z = fmaf(f2.z, a2, acc.z); acc.w = fmaf(f2.w, a2, acc.w);
        acc.x = fmaf(f3.x, a3, acc.x); acc.y = fmaf(f3.y, a3, acc.y);
        acc.z = fmaf(f3.z, a3, acc.z); acc.w = fmaf(f3.w, a3, acc.w);
    }
    for (; i < end; i++) {
        int s0 = __ldg(&g_esrc[i]);
        float a = 0.f;
        if (lane < 4) {
            float e = g_el[s0 * HH + lane] + er16;
            e = (e > 0.f) ? e : NEG_SLOPE * e;
            a = __expf(e);
        }
        float a0 = __shfl_sync(0xffffffffu, a, hd);
        dsum += a0;
        float4 f0 = ((const float4*)g_feat)[(size_t)s0 * (IN_DIM / 4) + lane];
        acc.x = fmaf(f0.x, a0, acc.x); acc.y = fmaf(f0.y, a0, acc.y);
        acc.z = fmaf(f0.z, a0, acc.z); acc.w = fmaf(f0.w, a0, acc.w);
    }
    float inv = (dsum > 0.f) ? (1.f / dsum) : 0.f;
    float4 b = ((const float4*)bgat)[lane];
    float4 o;
    o.x = acc.x * inv + b.x; o.y = acc.y * inv + b.y;
    o.z = acc.z * inv + b.z; o.w = acc.w * inv + b.w;
    o.x = (o.x > 0.f) ? o.x : expm1f(o.x);
    o.y = (o.y > 0.f) ? o.y : expm1f(o.y);
    o.z = (o.z > 0.f) ? o.z : expm1f(o.z);
    o.w = (o.w > 0.f) ? o.w : expm1f(o.w);
    ((float4*)g_hg)[(size_t)gw * (IN_DIM / 4) + lane] = o;
}

// ---------------- node: proj + gate + blend, 3-region smem (R11) --------
__global__ void __launch_bounds__(NTHR, 1) k_node_tc(
    const float* __restrict__ ctx, const float* __restrict__ bp,
    const float* __restrict__ bg, float* __restrict__ out) {
    extern __shared__ __align__(16) unsigned short sm[];
    unsigned short* Ahi = sm;
    unsigned short* Alo = sm + TILE_U16;
    unsigned short* Bt  = sm + 2 * TILE_U16;
    unsigned short* Chi = sm + 4 * TILE_U16;
    unsigned short* Clo = sm + 5 * TILE_U16;
    int tid = threadIdx.x, wid = tid >> 5, lane = tid & 31;
    int g = lane >> 2, t = lane & 3;
    long nodebase = (long)blockIdx.x * MTILE;
    int m0 = (wid >> 2) * 32, n0 = (wid & 3) * 32;

    fill_A(Ahi, Alo, g_hg, nodebase, tid);
    fill_A(Chi, Clo, ctx, nodebase, tid);
    copy_B(Bt, g_WpT, tid);
    __syncthreads();

    float acc[2][4][4];
#pragma unroll
    for (int a = 0; a < 2; a++)
#pragma unroll
        for (int b = 0; b < 4; b++)
#pragma unroll
            for (int c = 0; c < 4; c++) acc[a][b][c] = 0.f;

    gemm_tile<4>(acc, (const uint32_t*)Ahi, (const uint32_t*)Alo,
                 (const uint32_t*)Bt, (const uint32_t*)(Bt + TILE_U16), m0, n0, g, t);
    __syncthreads();

    {
        uint32_t* H = (uint32_t*)Ahi;
        uint32_t* L = (uint32_t*)Alo;
#pragma unroll
        for (int nt = 0; nt < 4; nt++) {
            int col = n0 + nt * 8 + 2 * t;
            float2 bpv = *(const float2*)&bp[col];
#pragma unroll
            for (int mt = 0; mt < 2; mt++) {
                int r0 = m0 + mt * 16 + g, r1 = r0 + 8;
                float h0 = acc[mt][nt][0] + bpv.x, h1 = acc[mt][nt][1] + bpv.y;
                float h2 = acc[mt][nt][2] + bpv.x, h3 = acc[mt][nt][3] + bpv.y;
                uint32_t hi, lo;
                split2(h0, h1, hi, lo);
                H[(r0 * TS + col) >> 1] = hi;
                L[(r0 * TS + col) >> 1] = lo;
                split2(h2, h3, hi, lo);
                H[(r1 * TS + col) >> 1] = hi;
                L[(r1 * TS + col) >> 1] = lo;
            }
        }
    }
    copy_B(Bt, g_WgT, tid);
    __syncthreads();

#pragma unroll
    for (int a = 0; a < 2; a++)
#pragma unroll
        for (int b = 0; b < 4; b++)
#pragma unroll
            for (int c = 0; c < 4; c++) acc[a][b][c] = 0.f;
    gemm_tile<4>(acc, (const uint32_t*)Ahi, (const uint32_t*)Alo,
                 (const uint32_t*)Bt, (const uint32_t*)(Bt + TILE_U16), m0, n0, g, t);
    __syncthreads();

    copy_B(Bt, g_WgT + 2 * TILE_U16, tid);
    __syncthreads();
    gemm_tile<4>(acc, (const uint32_t*)Chi, (const uint32_t*)Clo,
                 (const uint32_t*)Bt, (const uint32_t*)(Bt + TILE_U16), m0, n0, g, t);

#pragma unroll
    for (int nt = 0; nt < 4; nt++) {
        int col = n0 + nt * 8 + 2 * t;
        float2 bgv = *(const float2*)&bg[col];
#pragma unroll
        for (int mt = 0; mt < 2; mt++) {
            int lr0 = m0 + mt * 16 + g, lr1 = lr0 + 8;
            long r0 = nodebase + lr0, r1 = nodebase + lr1;
            if (r0 < NN) {
                float2 cv = recon2(Chi, Clo, lr0 * TS + col);
                float2 hv = recon2(Ahi, Alo, lr0 * TS + col);
                float s0 = 1.f / (1.f + __expf(-(acc[mt][nt][0] + bgv.x)));
                float s1 = 1.f / (1.f + __expf(-(acc[mt][nt][1] + bgv.y)));
                *(float2*)&out[r0 * IN_DIM + col] =
                    make_float2(s0 * hv.x + (1.f - s0) * cv.x, s1 * hv.y + (1.f - s1) * cv.y);
            }
            if (r1 < NN) {
                float2 cv = recon2(Chi, Clo, lr1 * TS + col);
                float2 hv = recon2(Ahi, Alo, lr1 * TS + col);
                float s2 = 1.f / (1.f + __expf(-(acc[mt][nt][2] + bgv.x)));
                float s3 = 1.f / (1.f + __expf(-(acc[mt][nt][3] + bgv.y)));
                *(float2*)&out[r1 * IN_DIM + col] =
                    make_float2(s2 * hv.x + (1.f - s2) * cv.x, s3 * hv.y + (1.f - s3) * cv.y);
            }
        }
    }
}

// ---------------- launch ----------------
#define SMEM_FEAT (2 * TILE_B)     // 69632 (A tiles only; B direct from L2)
#define SMEM_NODE (6 * TILE_B)     // 208896

extern "C" void kernel_launch(void* const* d_in, const int* in_sizes, int n_in,
                              void* d_out, int out_size) {
    const float* h    = (const float*)d_in[0];
    const int*   src  = (const int*)d_in[1];
    const int*   dst  = (const int*)d_in[2];
    const float* ctx  = (const float*)d_in[3];
    const float* Wfc  = (const float*)d_in[4];
    const float* al   = (const float*)d_in[5];
    const float* ar   = (const float*)d_in[6];
    const float* bgat = (const float*)d_in[7];
    const float* Wp   = (const float*)d_in[8];
    const float* bp   = (const float*)d_in[9];
    const float* Wg   = (const float*)d_in[10];
    const float* bg   = (const float*)d_in[11];
    float* out = (float*)d_out;

    static int inited = 0;
    static cudaStream_t s1;
    static cudaEvent_t evA, evB;
    if (!inited) {
        cudaFuncSetAttribute(k_feat_tc, cudaFuncAttributeMaxDynamicSharedMemorySize, SMEM_FEAT);
        cudaFuncSetAttribute(k_node_tc, cudaFuncAttributeMaxDynamicSharedMemorySize, SMEM_NODE);
        cudaStreamCreateWithFlags(&s1, cudaStreamNonBlocking);
        cudaEventCreateWithFlags(&evA, cudaEventDisableTiming);
        cudaEventCreateWithFlags(&evB, cudaEventDisableTiming);
        inited = 1;
    }

    // fork: side stream does Wp/Wg prep + CSR build (R11's proven order)
    cudaEventRecord(evA, 0);
    cudaStreamWaitEvent(s1, evA, 0);
    k_prepw_pg<<<192, 256, 0, s1>>>(Wp, Wg);
    k_init<<<(NN + 255) / 256, 256, 0, s1>>>();
    k_hist<<<(EE + 255) / 256, 256, 0, s1>>>(dst);
    k_scan1<<<NBLK_SCAN, 256, 0, s1>>>();
    k_scan2<<<1, 256, 0, s1>>>();
    k_scatter<<<(EE + 255) / 256, 256, 0, s1>>>(src, dst);
    cudaEventRecord(evB, s1);

    // main: Wfc prep, feat
    k_prepw_fc<<<64, 256>>>(Wfc);
    k_feat_tc<<<NCTA_GEMM, NTHR, SMEM_FEAT>>>(h, al, ar);

    // join, aggregate, node
    cudaStreamWaitEvent(0, evB, 0);
    k_agg<<<(NN * 32 + 255) / 256, 256>>>(bgat);
    k_node_tc<<<NCTA_GEMM, NTHR, SMEM_NODE>>>(ctx, bp, bg, out);
}

// round 17
// speedup vs baseline: 1.3332x; 1.0076x over previous
#include <cuda_runtime.h>
#include <cuda_bf16.h>
#include <math.h>
#include <stdint.h>

#define NN 50000
#define EE 800000
#define IN_DIM 128
#define HH 4
#define NEG_SLOPE 0.2f
#define NBLK_SCAN 196
#define MTILE 128
#define NCTA_GEMM 391
#define TS 136
#define TILE_U16 (128 * TS)
#define TILE_B (TILE_U16 * 2)
#define NTHR 512

// ---------------- scratch ----------------
__device__ float g_feat[(size_t)NN * IN_DIM];
__device__ float g_el[NN * HH];
__device__ float g_er[NN * HH];
__device__ float g_hg[(size_t)NN * IN_DIM];
__device__ int   g_cnt[NN];
__device__ int   g_off[NN];
__device__ int   g_cur[NN];
__device__ int   g_esrc[EE];
__device__ int   g_bsum[256];
__device__ __align__(16) unsigned short g_WfcT[2 * TILE_U16];
__device__ __align__(16) unsigned short g_WpT[2 * TILE_U16];
__device__ __align__(16) unsigned short g_WgT[4 * TILE_U16];

// ---------------- helpers ----------------
__device__ __forceinline__ unsigned short bfb(__nv_bfloat16 v) {
    return *reinterpret_cast<unsigned short*>(&v);
}
__device__ __forceinline__ void split2(float x0, float x1, uint32_t& hi, uint32_t& lo) {
    __nv_bfloat16 h0 = __float2bfloat16(x0), h1 = __float2bfloat16(x1);
    __nv_bfloat16 l0 = __float2bfloat16(x0 - __bfloat162float(h0));
    __nv_bfloat16 l1 = __float2bfloat16(x1 - __bfloat162float(h1));
    hi = (uint32_t)bfb(h0) | ((uint32_t)bfb(h1) << 16);
    lo = (uint32_t)bfb(l0) | ((uint32_t)bfb(l1) << 16);
}
__device__ __forceinline__ float2 recon2(const unsigned short* Hi, const unsigned short* Lo, int idx) {
    __nv_bfloat162 h = *(const __nv_bfloat162*)&Hi[idx];
    __nv_bfloat162 l = *(const __nv_bfloat162*)&Lo[idx];
    float2 hf = __bfloat1622float2(h);
    float2 lf = __bfloat1622float2(l);
    return make_float2(hf.x + lf.x, hf.y + lf.y);
}
__device__ __forceinline__ void hmma(float* c, uint32_t a0, uint32_t a1, uint32_t a2, uint32_t a3,
                                     uint32_t b0, uint32_t b1) {
    asm volatile(
        "mma.sync.aligned.m16n8k16.row.col.f32.bf16.bf16.f32 "
        "{%0,%1,%2,%3}, {%4,%5,%6,%7}, {%8,%9}, {%0,%1,%2,%3};"
        : "+f"(c[0]), "+f"(c[1]), "+f"(c[2]), "+f"(c[3])
        : "r"(a0), "r"(a1), "r"(a2), "r"(a3), "r"(b0), "r"(b1));
}

template <int NT>
__device__ __forceinline__ void gemm_tile(float acc[2][NT][4],
    const uint32_t* Ahi, const uint32_t* Alo,
    const uint32_t* Bhi, const uint32_t* Blo,
    int m0, int n0, int g, int t) {
#pragma unroll
    for (int ks = 0; ks < 8; ks++) {
        int k0 = ks * 16;
        uint32_t ah[2][4], al[2][4];
#pragma unroll
        for (int mt = 0; mt < 2; mt++) {
            int r = m0 + mt * 16 + g;
            int i0 = (r * TS + k0 + 2 * t) >> 1;
            int i1 = ((r + 8) * TS + k0 + 2 * t) >> 1;
            ah[mt][0] = Ahi[i0]; ah[mt][1] = Ahi[i1];
            ah[mt][2] = Ahi[i0 + 4]; ah[mt][3] = Ahi[i1 + 4];
            al[mt][0] = Alo[i0]; al[mt][1] = Alo[i1];
            al[mt][2] = Alo[i0 + 4]; al[mt][3] = Alo[i1 + 4];
        }
#pragma unroll
        for (int nt = 0; nt < NT; nt++) {
            int c = n0 + nt * 8 + g;
            int bi = (c * TS + k0 + 2 * t) >> 1;
            uint32_t bh0 = Bhi[bi], bh1 = Bhi[bi + 4];
            uint32_t bl0 = Blo[bi], bl1 = Blo[bi + 4];
#pragma unroll
            for (int mt = 0; mt < 2; mt++) {
                hmma(acc[mt][nt], ah[mt][0], ah[mt][1], ah[mt][2], ah[mt][3], bh0, bh1);
                hmma(acc[mt][nt], ah[mt][0], ah[mt][1], ah[mt][2], ah[mt][3], bl0, bl1);
                hmma(acc[mt][nt], al[mt][0], al[mt][1], al[mt][2], al[mt][3], bh0, bh1);
            }
        }
    }
}

__device__ __forceinline__ void fill_A(unsigned short* Ahi, unsigned short* Alo,
                                       const float* __restrict__ src, long nodebase,
                                       int tid) {
    int m = tid >> 2, q = tid & 3;
    long node = nodebase + m;
    const float* row = src + node * IN_DIM + q * 32;
    uint32_t* H = (uint32_t*)Ahi;
    uint32_t* L = (uint32_t*)Alo;
#pragma unroll
    for (int k4 = 0; k4 < 32; k4 += 4) {
        float4 v = make_float4(0.f, 0.f, 0.f, 0.f);
        if (node < NN) v = *(const float4*)(row + k4);
        uint32_t h01, l01, h23, l23;
        split2(v.x, v.y, h01, l01);
        split2(v.z, v.w, h23, l23);
        int idx = (m * TS + q * 32 + k4) >> 1;
        H[idx] = h01; H[idx + 1] = h23;
        L[idx] = l01; L[idx + 1] = l23;
    }
}

__device__ __forceinline__ void copy_B(unsigned short* dst, const unsigned short* src, int tid) {
    const uint4* s = (const uint4*)src;
    uint4* d = (uint4*)dst;
#pragma unroll
    for (int i = tid; i < 2 * TILE_B / 16; i += NTHR) d[i] = s[i];
}

// ---------------- small kernels ----------------
__global__ void k_init() {
    int i = blockIdx.x * blockDim.x + threadIdx.x;
    if (i < NN) g_cnt[i] = 0;
}

__global__ void k_hist(const int* __restrict__ dst) {
    int e = blockIdx.x * blockDim.x + threadIdx.x;
    if (e < EE) atomicAdd(&g_cnt[dst[e]], 1);
}

__global__ void k_prepw_fc(const float* __restrict__ Wfc) {
    int id = blockIdx.x * 256 + threadIdx.x;
    if (id >= 16384) return;
    int n = id >> 7, k = id & 127;
    float w = Wfc[k * 128 + n];
    __nv_bfloat16 hi = __float2bfloat16(w);
    __nv_bfloat16 lo = __float2bfloat16(w - __bfloat162float(hi));
    g_WfcT[n * TS + k] = bfb(hi);
    g_WfcT[TILE_U16 + n * TS + k] = bfb(lo);
}

__global__ void k_prepw_pg(const float* __restrict__ Wp, const float* __restrict__ Wg) {
    int id = blockIdx.x * 256 + threadIdx.x;
    if (id < 16384) {
        int n = id >> 7, k = id & 127;
        float w = Wp[k * 128 + n];
        __nv_bfloat16 hi = __float2bfloat16(w);
        __nv_bfloat16 lo = __float2bfloat16(w - __bfloat162float(hi));
        g_WpT[n * TS + k] = bfb(hi);
        g_WpT[TILE_U16 + n * TS + k] = bfb(lo);
    } else if (id < 49152) {
        int e = id - 16384;
        int n = e & 127, k = e >> 7;
        float w = Wg[k * 128 + n];
        int stage = k >> 7, kk = k & 127;
        __nv_bfloat16 hi = __float2bfloat16(w);
        __nv_bfloat16 lo = __float2bfloat16(w - __bfloat162float(hi));
        g_WgT[stage * 2 * TILE_U16 + n * TS + kk] = bfb(hi);
        g_WgT[stage * 2 * TILE_U16 + TILE_U16 + n * TS + kk] = bfb(lo);
    }
}

// ---------------- feat = h @ W_fc, fused el/er (R11 config) -------------
__global__ void __launch_bounds__(NTHR, 1) k_feat_tc(const float* __restrict__ h,
                                                     const float* __restrict__ al,
                                                     const float* __restrict__ ar) {
    extern __shared__ __align__(16) unsigned short sm[];
    unsigned short* Ahi = sm;
    unsigned short* Alo = sm + TILE_U16;
    unsigned short* Bt  = sm + 2 * TILE_U16;
    int tid = threadIdx.x, wid = tid >> 5, lane = tid & 31;
    int g = lane >> 2, t = lane & 3;
    long nodebase = (long)blockIdx.x * MTILE;

    fill_A(Ahi, Alo, h, nodebase, tid);
    copy_B(Bt, g_WfcT, tid);
    __syncthreads();

    float acc[2][4][4];
#pragma unroll
    for (int a = 0; a < 2; a++)
#pragma unroll
        for (int b = 0; b < 4; b++)
#pragma unroll
            for (int c = 0; c < 4; c++) acc[a][b][c] = 0.f;

    int m0 = (wid >> 2) * 32, n0 = (wid & 3) * 32;
    gemm_tile<4>(acc, (const uint32_t*)Ahi, (const uint32_t*)Alo,
                 (const uint32_t*)Bt, (const uint32_t*)(Bt + TILE_U16), m0, n0, g, t);

    int head = wid & 3;
    float pl[4] = {0.f, 0.f, 0.f, 0.f};
    float pr[4] = {0.f, 0.f, 0.f, 0.f};
#pragma unroll
    for (int nt = 0; nt < 4; nt++) {
        int col = n0 + nt * 8 + 2 * t;
        float a0 = __ldg(&al[col]), a1 = __ldg(&al[col + 1]);
        float b0 = __ldg(&ar[col]), b1 = __ldg(&ar[col + 1]);
#pragma unroll
        for (int mt = 0; mt < 2; mt++) {
            pl[2 * mt]     += acc[mt][nt][0] * a0 + acc[mt][nt][1] * a1;
            pl[2 * mt + 1] += acc[mt][nt][2] * a0 + acc[mt][nt][3] * a1;
            pr[2 * mt]     += acc[mt][nt][0] * b0 + acc[mt][nt][1] * b1;
            pr[2 * mt + 1] += acc[mt][nt][2] * b0 + acc[mt][nt][3] * b1;
        }
    }
#pragma unroll
    for (int off = 1; off <= 2; off <<= 1) {
#pragma unroll
        for (int i = 0; i < 4; i++) {
            pl[i] += __shfl_xor_sync(0xffffffffu, pl[i], off);
            pr[i] += __shfl_xor_sync(0xffffffffu, pr[i], off);
        }
    }
    if (t == 0) {
#pragma unroll
        for (int mt = 0; mt < 2; mt++) {
            long r0 = nodebase + m0 + mt * 16 + g;
            long r1 = r0 + 8;
            if (r0 < NN) { g_el[r0 * HH + head] = pl[2 * mt];     g_er[r0 * HH + head] = pr[2 * mt]; }
            if (r1 < NN) { g_el[r1 * HH + head] = pl[2 * mt + 1]; g_er[r1 * HH + head] = pr[2 * mt + 1]; }
        }
    }

#pragma unroll
    for (int mt = 0; mt < 2; mt++) {
        long r0 = nodebase + m0 + mt * 16 + g;
        long r1 = r0 + 8;
#pragma unroll
        for (int nt = 0; nt < 4; nt++) {
            int col = n0 + nt * 8 + 2 * t;
            if (r0 < NN) *(float2*)&g_feat[r0 * IN_DIM + col] = make_float2(acc[mt][nt][0], acc[mt][nt][1]);
            if (r1 < NN) *(float2*)&g_feat[r1 * IN_DIM + col] = make_float2(acc[mt][nt][2], acc[mt][nt][3]);
        }
    }
}

// ---------------- scans / scatter ----------------
__global__ void k_scan1() {
    __shared__ int s[256];
    int i = blockIdx.x * 256 + threadIdx.x;
    int v = (i < NN) ? g_cnt[i] : 0;
    if (i < NN) g_cur[i] = 0;      // folded from k_init (ordered before k_scatter on s1)
    s[threadIdx.x] = v;
    __syncthreads();
#pragma unroll
    for (int off = 1; off < 256; off <<= 1) {
        int tv = (threadIdx.x >= off) ? s[threadIdx.x - off] : 0;
        __syncthreads();
        s[threadIdx.x] += tv;
        __syncthreads();
    }
    if (i < NN) g_off[i] = s[threadIdx.x] - v;
    if (threadIdx.x == 255) g_bsum[blockIdx.x] = s[255];
}

__global__ void k_scan2() {
    __shared__ int s[256];
    int t = threadIdx.x;
    int v = (t < NBLK_SCAN) ? g_bsum[t] : 0;
    s[t] = v;
    __syncthreads();
#pragma unroll
    for (int off = 1; off < 256; off <<= 1) {
        int tv = (t >= off) ? s[t - off] : 0;
        __syncthreads();
        s[t] += tv;
        __syncthreads();
    }
    if (t < NBLK_SCAN) g_bsum[t] = s[t] - v;
}

__global__ void k_scatter(const int* __restrict__ src, const int* __restrict__ dst) {
    int e = blockIdx.x * blockDim.x + threadIdx.x;
    if (e >= EE) return;
    int d = dst[e];
    int pos = atomicAdd(&g_cur[d], 1);
    g_esrc[g_off[d] + g_bsum[d >> 8] + pos] = src[e];
}

// ---------------- aggregate: warp per node, 4 edges/iter ----------------
__global__ void k_agg(const float* __restrict__ bgat) {
    int gw = (blockIdx.x * blockDim.x + threadIdx.x) >> 5;
    if (gw >= NN) return;
    int lane = threadIdx.x & 31;
    int beg = g_off[gw] + g_bsum[gw >> 8];
    int end = beg + g_cnt[gw];
    float er_h = (lane < HH) ? g_er[gw * HH + lane] : 0.f;
    float er16 = __shfl_sync(0xffffffffu, er_h, lane & 3);
    int hd = lane >> 3;
    float4 acc = make_float4(0.f, 0.f, 0.f, 0.f);
    float dsum = 0.f;
    int i = beg;
    for (; i + 3 < end; i += 4) {
        int s0 = __ldg(&g_esrc[i]);
        int s1 = __ldg(&g_esrc[i + 1]);
        int s2 = __ldg(&g_esrc[i + 2]);
        int s3 = __ldg(&g_esrc[i + 3]);
        float a = 0.f;
        if (lane < 16) {
            int eix = lane >> 2;
            int sx = (eix == 0) ? s0 : (eix == 1) ? s1 : (eix == 2) ? s2 : s3;
            float e = g_el[sx * HH + (lane & 3)] + er16;
            e = (e > 0.f) ? e : NEG_SLOPE * e;
            a = __expf(e);
        }
        float a0 = __shfl_sync(0xffffffffu, a, hd);
        float a1 = __shfl_sync(0xffffffffu, a, 4 + hd);
        float a2 = __shfl_sync(0xffffffffu, a, 8 + hd);
        float a3 = __shfl_sync(0xffffffffu, a, 12 + hd);
        dsum += (a0 + a1) + (a2 + a3);
        float4 f0 = ((const float4*)g_feat)[(size_t)s0 * (IN_DIM / 4) + lane];
        float4 f1 = ((const float4*)g_feat)[(size_t)s1 * (IN_DIM / 4) + lane];
        float4 f2 = ((const float4*)g_feat)[(size_t)s2 * (IN_DIM / 4) + lane];
        float4 f3 = ((const float4*)g_feat)[(size_t)s3 * (IN_DIM / 4) + lane];
        acc.x = fmaf(f0.x, a0, acc.x); acc.y = fmaf(f0.y, a0, acc.y);
        acc.z = fmaf(f0.z, a0, acc.z); acc.w = fmaf(f0.w, a0, acc.w);
        acc.x = fmaf(f1.x, a1, acc.x); acc.y = fmaf(f1.y, a1, acc.y);
        acc.z = fmaf(f1.z, a1, acc.z); acc.w = fmaf(f1.w, a1, acc.w);
        acc.x = fmaf(f2.x, a2, acc.x); acc.y = fmaf(f2.y, a2, acc.y);
        acc.z = fmaf(f2.z, a2, acc.z); acc.w = fmaf(f2.w, a2, acc.w);
        acc.x = fmaf(f3.x, a3, acc.x); acc.y = fmaf(f3.y, a3, acc.y);
        acc.z = fmaf(f3.z, a3, acc.z); acc.w = fmaf(f3.w, a3, acc.w);
    }
    for (; i < end; i++) {
        int s0 = __ldg(&g_esrc[i]);
        float a = 0.f;
        if (lane < 4) {
            float e = g_el[s0 * HH + lane] + er16;
            e = (e > 0.f) ? e : NEG_SLOPE * e;
            a = __expf(e);
        }
        float a0 = __shfl_sync(0xffffffffu, a, hd);
        dsum += a0;
        float4 f0 = ((const float4*)g_feat)[(size_t)s0 * (IN_DIM / 4) + lane];
        acc.x = fmaf(f0.x, a0, acc.x); acc.y = fmaf(f0.y, a0, acc.y);
        acc.z = fmaf(f0.z, a0, acc.z); acc.w = fmaf(f0.w, a0, acc.w);
    }
    float inv = (dsum > 0.f) ? (1.f / dsum) : 0.f;
    float4 b = ((const float4*)bgat)[lane];
    float4 o;
    o.x = acc.x * inv + b.x; o.y = acc.y * inv + b.y;
    o.z = acc.z * inv + b.z; o.w = acc.w * inv + b.w;
    o.x = (o.x > 0.f) ? o.x : expm1f(o.x);
    o.y = (o.y > 0.f) ? o.y : expm1f(o.y);
    o.z = (o.z > 0.f) ? o.z : expm1f(o.z);
    o.w = (o.w > 0.f) ? o.w : expm1f(o.w);
    ((float4*)g_hg)[(size_t)gw * (IN_DIM / 4) + lane] = o;
}

// ---------------- node: proj + gate + blend, 3-region smem (R11) --------
__global__ void __launch_bounds__(NTHR, 1) k_node_tc(
    const float* __restrict__ ctx, const float* __restrict__ bp,
    const float* __restrict__ bg, float* __restrict__ out) {
    extern __shared__ __align__(16) unsigned short sm[];
    unsigned short* Ahi = sm;
    unsigned short* Alo = sm + TILE_U16;
    unsigned short* Bt  = sm + 2 * TILE_U16;
    unsigned short* Chi = sm + 4 * TILE_U16;
    unsigned short* Clo = sm + 5 * TILE_U16;
    int tid = threadIdx.x, wid = tid >> 5, lane = tid & 31;
    int g = lane >> 2, t = lane & 3;
    long nodebase = (long)blockIdx.x * MTILE;
    int m0 = (wid >> 2) * 32, n0 = (wid & 3) * 32;

    fill_A(Ahi, Alo, g_hg, nodebase, tid);
    fill_A(Chi, Clo, ctx, nodebase, tid);
    copy_B(Bt, g_WpT, tid);
    __syncthreads();

    // phase 1: hp = hg @ Wp^T
    float acc[2][4][4];
#pragma unroll
    for (int a = 0; a < 2; a++)
#pragma unroll
        for (int b = 0; b < 4; b++)
#pragma unroll
            for (int c = 0; c < 4; c++) acc[a][b][c] = 0.f;

    gemm_tile<4>(acc, (const uint32_t*)Ahi, (const uint32_t*)Alo,
                 (const uint32_t*)Bt, (const uint32_t*)(Bt + TILE_U16), m0, n0, g, t);
    __syncthreads();

    // hp = acc + bias -> re-split into A tiles (epilogue hp source too)
    {
        uint32_t* H = (uint32_t*)Ahi;
        uint32_t* L = (uint32_t*)Alo;
#pragma unroll
        for (int nt = 0; nt < 4; nt++) {
            int col = n0 + nt * 8 + 2 * t;
            float2 bpv = *(const float2*)&bp[col];
#pragma unroll
            for (int mt = 0; mt < 2; mt++) {
                int r0 = m0 + mt * 16 + g, r1 = r0 + 8;
                float h0 = acc[mt][nt][0] + bpv.x, h1 = acc[mt][nt][1] + bpv.y;
                float h2 = acc[mt][nt][2] + bpv.x, h3 = acc[mt][nt][3] + bpv.y;
                uint32_t hi, lo;
                split2(h0, h1, hi, lo);
                H[(r0 * TS + col) >> 1] = hi;
                L[(r0 * TS + col) >> 1] = lo;
                split2(h2, h3, hi, lo);
                H[(r1 * TS + col) >> 1] = hi;
                L[(r1 * TS + col) >> 1] = lo;
            }
        }
    }
    copy_B(Bt, g_WgT, tid);
    __syncthreads();

    // phase 2: gate = hp @ Wg1^T
#pragma unroll
    for (int a = 0; a < 2; a++)
#pragma unroll
        for (int b = 0; b < 4; b++)
#pragma unroll
            for (int c = 0; c < 4; c++) acc[a][b][c] = 0.f;
    gemm_tile<4>(acc, (const uint32_t*)Ahi, (const uint32_t*)Alo,
                 (const uint32_t*)Bt, (const uint32_t*)(Bt + TILE_U16), m0, n0, g, t);
    __syncthreads();

    // phase 3: gate += ctx @ Wg2^T
    copy_B(Bt, g_WgT + 2 * TILE_U16, tid);
    __syncthreads();
    gemm_tile<4>(acc, (const uint32_t*)Chi, (const uint32_t*)Clo,
                 (const uint32_t*)Bt, (const uint32_t*)(Bt + TILE_U16), m0, n0, g, t);

    // epilogue
#pragma unroll
    for (int nt = 0; nt < 4; nt++) {
        int col = n0 + nt * 8 + 2 * t;
        float2 bgv = *(const float2*)&bg[col];
#pragma unroll
        for (int mt = 0; mt < 2; mt++) {
            int lr0 = m0 + mt * 16 + g, lr1 = lr0 + 8;
            long r0 = nodebase + lr0, r1 = nodebase + lr1;
            if (r0 < NN) {
                float2 cv = recon2(Chi, Clo, lr0 * TS + col);
                float2 hv = recon2(Ahi, Alo, lr0 * TS + col);
                float s0 = 1.f / (1.f + __expf(-(acc[mt][nt][0] + bgv.x)));
                float s1 = 1.f / (1.f + __expf(-(acc[mt][nt][1] + bgv.y)));
                *(float2*)&out[r0 * IN_DIM + col] =
                    make_float2(s0 * hv.x + (1.f - s0) * cv.x, s1 * hv.y + (1.f - s1) * cv.y);
            }
            if (r1 < NN) {
                float2 cv = recon2(Chi, Clo, lr1 * TS + col);
                float2 hv = recon2(Ahi, Alo, lr1 * TS + col);
                float s2 = 1.f / (1.f + __expf(-(acc[mt][nt][2] + bgv.x)));
                float s3 = 1.f / (1.f + __expf(-(acc[mt][nt][3] + bgv.y)));
                *(float2*)&out[r1 * IN_DIM + col] =
                    make_float2(s2 * hv.x + (1.f - s2) * cv.x, s3 * hv.y + (1.f - s3) * cv.y);
            }
        }
    }
}

// ---------------- launch ----------------
#define SMEM_FEAT (4 * TILE_B)     // 139264
#define SMEM_NODE (6 * TILE_B)     // 208896

extern "C" void kernel_launch(void* const* d_in, const int* in_sizes, int n_in,
                              void* d_out, int out_size) {
    const float* h    = (const float*)d_in[0];
    const int*   src  = (const int*)d_in[1];
    const int*   dst  = (const int*)d_in[2];
    const float* ctx  = (const float*)d_in[3];
    const float* Wfc  = (const float*)d_in[4];
    const float* al   = (const float*)d_in[5];
    const float* ar   = (const float*)d_in[6];
    const float* bgat = (const float*)d_in[7];
    const float* Wp   = (const float*)d_in[8];
    const float* bp   = (const float*)d_in[9];
    const float* Wg   = (const float*)d_in[10];
    const float* bg   = (const float*)d_in[11];
    float* out = (float*)d_out;

    static int inited = 0;
    static cudaStream_t s1;
    static cudaEvent_t evA, evB;
    if (!inited) {
        cudaFuncSetAttribute(k_feat_tc, cudaFuncAttributeMaxDynamicSharedMemorySize, SMEM_FEAT);
        cudaFuncSetAttribute(k_node_tc, cudaFuncAttributeMaxDynamicSharedMemorySize, SMEM_NODE);
        cudaStreamCreateWithFlags(&s1, cudaStreamNonBlocking);
        cudaEventCreateWithFlags(&evA, cudaEventDisableTiming);
        cudaEventCreateWithFlags(&evB, cudaEventDisableTiming);
        inited = 1;
    }

    // fork: side stream does Wp/Wg prep + CSR build (R11's proven order)
    cudaEventRecord(evA, 0);
    cudaStreamWaitEvent(s1, evA, 0);
    k_prepw_pg<<<192, 256, 0, s1>>>(Wp, Wg);
    k_init<<<(NN + 255) / 256, 256, 0, s1>>>();
    k_hist<<<(EE + 255) / 256, 256, 0, s1>>>(dst);
    k_scan1<<<NBLK_SCAN, 256, 0, s1>>>();
    k_scan2<<<1, 256, 0, s1>>>();
    k_scatter<<<(EE + 255) / 256, 256, 0, s1>>>(src, dst);
    cudaEventRecord(evB, s1);

    // main: Wfc prep, feat
    k_prepw_fc<<<64, 256>>>(Wfc);
    k_feat_tc<<<NCTA_GEMM, NTHR, SMEM_FEAT>>>(h, al, ar);

    // join, aggregate, node
    cudaStreamWaitEvent(0, evB, 0);
    k_agg<<<(NN * 32 + 255) / 256, 256>>>(bgat);
    k_node_tc<<<NCTA_GEMM, NTHR, SMEM_NODE>>>(ctx, bp, bg, out);
}